// round 2
// baseline (speedup 1.0000x reference)
#include <cuda_runtime.h>
#include <cuda_bf16.h>
#include <cstdint>
#include <cstddef>

// ---------------------------------------------------------------------------
// KANLayer as one big GEMM on the base-ISA tensor path (mma.sync bf16):
//   out[4096,2048] = X_ext[4096,18432] @ W_ext[2048,18432]^T
//   X_ext[:,0:2048]     = x
//   X_ext[:,2048+i*8+g] = relu(x[:,i] - knots[g])
//   W_ext[:,0:2048]     = base_weight
//   W_ext[:,2048+i*8+g] = 0.1*spline_weight[:,i,g]
// Split-bf16 (hi+lo), 3 products (hiHi + hiLo + loHi) -> fp32-grade accuracy.
// tcgen05 is NOT usable: harness PTX pass targets compute_103 (no 'a').
// ---------------------------------------------------------------------------

#define B_ROWS 4096
#define O_COLS 2048
#define I_FEAT 2048
#define G_KNOT 8
#define K_EXT  (I_FEAT + I_FEAT * G_KNOT)   // 18432
#define K_CHUNK 64                           // bf16 per chunk (128B rows)
#define N_CHUNKS (K_EXT / K_CHUNK)           // 288

// CTA tile 128x128, 256 threads = 8 warps (4 m x 2 n), warp tile 32x64.
#define STAGE_BYTES 65536                    // Ahi16K+Alo16K+Bhi16K+Blo16K
#define SMEM_BYTES  (2 * STAGE_BYTES)        // 131072

// --- scratch (device-global; no allocation allowed in kernel_launch) ---
__device__ __nv_bfloat16 g_Ahi[(size_t)B_ROWS * K_EXT];
__device__ __nv_bfloat16 g_Alo[(size_t)B_ROWS * K_EXT];
__device__ __nv_bfloat16 g_Bhi[(size_t)O_COLS * K_EXT];
__device__ __nv_bfloat16 g_Blo[(size_t)O_COLS * K_EXT];

// ------------------------------ PTX helpers --------------------------------
__device__ __forceinline__ uint32_t smem_to_u32(const void* p) {
    uint32_t a;
    asm("{ .reg .u64 t; cvta.to.shared.u64 t, %1; cvt.u32.u64 %0, t; }"
        : "=r"(a) : "l"(p));
    return a;
}

#define CP_ASYNC16(dst, src) \
    asm volatile("cp.async.cg.shared.global [%0], [%1], 16;" \
                 :: "r"(dst), "l"(src))
#define CP_COMMIT() asm volatile("cp.async.commit_group;" ::: "memory")
#define CP_WAIT1()  asm volatile("cp.async.wait_group 1;" ::: "memory")

#define LDSM4(r, addr) \
    asm volatile("ldmatrix.sync.aligned.m8n8.x4.shared.b16 {%0,%1,%2,%3}, [%4];" \
        : "=r"((r)[0]), "=r"((r)[1]), "=r"((r)[2]), "=r"((r)[3]) : "r"(addr))

#define MMA_BF16(d, a, b) \
    asm volatile("mma.sync.aligned.m16n8k16.row.col.f32.bf16.bf16.f32 " \
        "{%0,%1,%2,%3}, {%4,%5,%6,%7}, {%8,%9}, {%0,%1,%2,%3};" \
        : "+f"((d)[0]), "+f"((d)[1]), "+f"((d)[2]), "+f"((d)[3]) \
        : "r"((a)[0]), "r"((a)[1]), "r"((a)[2]), "r"((a)[3]), \
          "r"((b)[0]), "r"((b)[1]))

// --------------------------- preprocessing kernels --------------------------

__global__ void prep_w_kernel(const float* __restrict__ base_w,
                              const float* __restrict__ spline_w) {
    const int k = blockIdx.x * 256 + threadIdx.x;
    const int o = blockIdx.y;
    float w;
    if (k < I_FEAT) {
        w = base_w[o * I_FEAT + k];
    } else {
        w = 0.1f * spline_w[o * (I_FEAT * G_KNOT) + (k - I_FEAT)];
    }
    __nv_bfloat16 hi = __float2bfloat16(w);
    float lo = w - __bfloat162float(hi);
    const size_t idx = (size_t)o * K_EXT + k;
    g_Bhi[idx] = hi;
    g_Blo[idx] = __float2bfloat16(lo);
}

__global__ void prep_x_kernel(const float* __restrict__ x,
                              const float* __restrict__ knots) {
    const int k = blockIdx.x * 256 + threadIdx.x;
    const int b = blockIdx.y;
    float v;
    if (k < I_FEAT) {
        v = x[(size_t)b * I_FEAT + k];
    } else {
        const int r = k - I_FEAT;
        const int i = r >> 3;
        const int g = r & 7;
        v = fmaxf(x[(size_t)b * I_FEAT + i] - __ldg(&knots[g]), 0.0f);
    }
    __nv_bfloat16 hi = __float2bfloat16(v);
    float lo = v - __bfloat162float(hi);
    const size_t idx = (size_t)b * K_EXT + k;
    g_Ahi[idx] = hi;
    g_Alo[idx] = __float2bfloat16(lo);
}

// ------------------------------ GEMM kernel ---------------------------------

// Issue cp.async for one 128-row x 128B chunk of each of the 4 matrices.
// Stage layout: [A_hi 16K][A_lo 16K][B_hi 16K][B_lo 16K], SW128-style XOR swizzle.
__device__ __forceinline__ void load_chunk(const __nv_bfloat16* gAh,
                                           const __nv_bfloat16* gAl,
                                           const __nv_bfloat16* gBh,
                                           const __nv_bfloat16* gBl,
                                           uint32_t st, int tid) {
    const __nv_bfloat16* gsrc[4] = {gAh, gAl, gBh, gBl};
#pragma unroll
    for (int m = 0; m < 4; ++m) {
        const uint32_t base = st + m * 16384;
        const char* g = reinterpret_cast<const char*>(gsrc[m]);
#pragma unroll
        for (int i = 0; i < 4; ++i) {
            const int idx = tid + i * 256;        // 0..1023
            const int row = idx >> 3;             // 0..127
            const int sub = idx & 7;              // 16B piece
            const uint32_t off = (uint32_t)(row * 128 + sub * 16);
            const uint32_t dst = base + (off ^ ((off >> 3) & 0x70u));
            const char* src = g + (size_t)row * (K_EXT * 2) + sub * 16;
            CP_ASYNC16(dst, src);
        }
    }
}

__global__ void __launch_bounds__(256, 1) kan_gemm(float* __restrict__ out) {
    extern __shared__ char smem[];
    const uint32_t sm0 = smem_to_u32(smem);
    const int tid = threadIdx.x;
    const int lane = tid & 31;
    const int warp = tid >> 5;
    const int wm = warp & 3;       // 4 warps along M
    const int wn = warp >> 2;      // 2 warps along N

    const size_t m0 = (size_t)blockIdx.y * 128;
    const size_t n0 = (size_t)blockIdx.x * 128;
    const __nv_bfloat16* pAh = g_Ahi + m0 * K_EXT;
    const __nv_bfloat16* pAl = g_Alo + m0 * K_EXT;
    const __nv_bfloat16* pBh = g_Bhi + n0 * K_EXT;
    const __nv_bfloat16* pBl = g_Blo + n0 * K_EXT;

    float acc[2][8][4] = {};

    // ldmatrix lane->row/koff mappings
    // A (x4 tiles in order: (m0-7,k0-7),(m8-15,k0-7),(m0-7,k8-15),(m8-15,k8-15))
    const int a_lr = (lane & 7) | (((lane >> 3) & 1) << 3);
    const int a_ko = (lane >> 4) << 4;
    // B (x4 tiles: (n0-7,k0-7),(n0-7,k8-15),(n8-15,k0-7),(n8-15,k8-15))
    const int b_lr = (lane & 7) | (((lane >> 4) & 1) << 3);
    const int b_ko = ((lane >> 3) & 1) << 4;
    const uint32_t xorl = (uint32_t)((lane & 7) << 4);

    uint32_t a_rowoff[2], b_rowoff[4];
#pragma unroll
    for (int mt = 0; mt < 2; ++mt)
        a_rowoff[mt] = (uint32_t)((wm * 32 + mt * 16 + a_lr) * 128);
#pragma unroll
    for (int nt2 = 0; nt2 < 4; ++nt2)
        b_rowoff[nt2] = (uint32_t)((wn * 64 + nt2 * 16 + b_lr) * 128);

    load_chunk(pAh, pAl, pBh, pBl, sm0, tid);
    CP_COMMIT();

    for (int c = 0; c < N_CHUNKS; ++c) {
        if (c + 1 < N_CHUNKS) {
            const int k1 = (c + 1) * K_CHUNK;
            load_chunk(pAh + k1, pAl + k1, pBh + k1, pBl + k1,
                       sm0 + (uint32_t)(((c + 1) & 1) * STAGE_BYTES), tid);
        }
        CP_COMMIT();
        CP_WAIT1();
        __syncthreads();

        const uint32_t sb = sm0 + (uint32_t)((c & 1) * STAGE_BYTES);
#pragma unroll
        for (int ks = 0; ks < 4; ++ks) {
            const uint32_t kb = (uint32_t)(ks * 32);
            uint32_t ah[2][4], al[2][4];
#pragma unroll
            for (int mt = 0; mt < 2; ++mt) {
                const uint32_t ad = sb + a_rowoff[mt] + ((kb + a_ko) ^ xorl);
                LDSM4(ah[mt], ad);
                LDSM4(al[mt], ad + 16384);
            }
            uint32_t bh[4][4], bl[4][4];
#pragma unroll
            for (int nt2 = 0; nt2 < 4; ++nt2) {
                const uint32_t bd = sb + 32768 + b_rowoff[nt2] + ((kb + b_ko) ^ xorl);
                LDSM4(bh[nt2], bd);
                LDSM4(bl[nt2], bd + 16384);
            }
#pragma unroll
            for (int mt = 0; mt < 2; ++mt) {
#pragma unroll
                for (int nt = 0; nt < 8; ++nt) {
                    uint32_t* bH = &bh[nt >> 1][(nt & 1) * 2];
                    uint32_t* bL = &bl[nt >> 1][(nt & 1) * 2];
                    MMA_BF16(acc[mt][nt], ah[mt], bH);   // hi * Hi
                    MMA_BF16(acc[mt][nt], ah[mt], bL);   // hi * Lo
                    MMA_BF16(acc[mt][nt], al[mt], bH);   // lo * Hi
                }
            }
        }
        __syncthreads();
    }

    // Epilogue: c-frag lane l holds D[l/4][(l%4)*2+{0,1}] and row+8.
    const int r = lane >> 2;
    const int cp2 = (lane & 3) * 2;
#pragma unroll
    for (int mt = 0; mt < 2; ++mt) {
#pragma unroll
        for (int nt = 0; nt < 8; ++nt) {
            const size_t row = m0 + wm * 32 + mt * 16 + r;
            const size_t col = n0 + wn * 64 + nt * 8 + cp2;
            float2 v0 = make_float2(acc[mt][nt][0], acc[mt][nt][1]);
            float2 v1 = make_float2(acc[mt][nt][2], acc[mt][nt][3]);
            *reinterpret_cast<float2*>(&out[row * O_COLS + col]) = v0;
            *reinterpret_cast<float2*>(&out[(row + 8) * O_COLS + col]) = v1;
        }
    }
}

// ------------------------------- launch -------------------------------------

extern "C" void kernel_launch(void* const* d_in, const int* in_sizes, int n_in,
                              void* d_out, int out_size) {
    const float* x        = (const float*)d_in[0];
    const float* base_w   = (const float*)d_in[1];
    const float* spline_w = (const float*)d_in[2];
    const float* knots    = (const float*)d_in[3];
    float* out = (float*)d_out;

    prep_w_kernel<<<dim3(K_EXT / 256, O_COLS), 256>>>(base_w, spline_w);
    prep_x_kernel<<<dim3(K_EXT / 256, B_ROWS), 256>>>(x, knots);

    cudaFuncSetAttribute(kan_gemm, cudaFuncAttributeMaxDynamicSharedMemorySize,
                         SMEM_BYTES);
    kan_gemm<<<dim3(O_COLS / 128, B_ROWS / 128), 256, SMEM_BYTES>>>(out);
}

// round 3
// speedup vs baseline: 1.1077x; 1.1077x over previous
#include <cuda_runtime.h>
#include <cuda_bf16.h>
#include <cstdint>
#include <cstddef>

// ---------------------------------------------------------------------------
// KANLayer as one big GEMM (mma.sync bf16, split-bf16 x3 products):
//   out[4096,2048] = X_ext[4096,18432] @ W_ext[2048,18432]^T
// Round 3: CTA tile 256x128 (warp tile 64x64), vectorized prep, raster swizzle.
// ---------------------------------------------------------------------------

#define B_ROWS 4096
#define O_COLS 2048
#define I_FEAT 2048
#define G_KNOT 8
#define K_EXT  (I_FEAT + I_FEAT * G_KNOT)   // 18432
#define K_CHUNK 64
#define N_CHUNKS (K_EXT / K_CHUNK)           // 288

#define M_TILE 256
#define N_TILE 128
// stage: [Ahi 32K][Alo 32K][Bhi 16K][Blo 16K] = 96KB
#define STAGE_BYTES 98304
#define SMEM_BYTES (2 * STAGE_BYTES)         // 196608

__device__ __nv_bfloat16 g_Ahi[(size_t)B_ROWS * K_EXT];
__device__ __nv_bfloat16 g_Alo[(size_t)B_ROWS * K_EXT];
__device__ __nv_bfloat16 g_Bhi[(size_t)O_COLS * K_EXT];
__device__ __nv_bfloat16 g_Blo[(size_t)O_COLS * K_EXT];

// ------------------------------ PTX helpers --------------------------------
__device__ __forceinline__ uint32_t smem_to_u32(const void* p) {
    uint32_t a;
    asm("{ .reg .u64 t; cvta.to.shared.u64 t, %1; cvt.u32.u64 %0, t; }"
        : "=r"(a) : "l"(p));
    return a;
}

#define CP_ASYNC16(dst, src) \
    asm volatile("cp.async.cg.shared.global [%0], [%1], 16;" \
                 :: "r"(dst), "l"(src))
#define CP_COMMIT() asm volatile("cp.async.commit_group;" ::: "memory")
#define CP_WAIT1()  asm volatile("cp.async.wait_group 1;" ::: "memory")

#define LDSM4(r, addr) \
    asm volatile("ldmatrix.sync.aligned.m8n8.x4.shared.b16 {%0,%1,%2,%3}, [%4];" \
        : "=r"((r)[0]), "=r"((r)[1]), "=r"((r)[2]), "=r"((r)[3]) : "r"(addr))

#define MMA_BF16(d, a, b) \
    asm volatile("mma.sync.aligned.m16n8k16.row.col.f32.bf16.bf16.f32 " \
        "{%0,%1,%2,%3}, {%4,%5,%6,%7}, {%8,%9}, {%0,%1,%2,%3};" \
        : "+f"((d)[0]), "+f"((d)[1]), "+f"((d)[2]), "+f"((d)[3]) \
        : "r"((a)[0]), "r"((a)[1]), "r"((a)[2]), "r"((a)[3]), \
          "r"((b)[0]), "r"((b)[1]))

// --------------------------- preprocessing kernels --------------------------

struct alignas(16) Pack8 { __nv_bfloat16 v[8]; };

__device__ __forceinline__ void split8(const float* v, Pack8& hi, Pack8& lo) {
#pragma unroll
    for (int j = 0; j < 8; ++j) {
        __nv_bfloat16 h = __float2bfloat16(v[j]);
        hi.v[j] = h;
        lo.v[j] = __float2bfloat16(v[j] - __bfloat162float(h));
    }
}

// grid (K_EXT/2048, O_COLS), 256 thr; thread -> 8 consecutive k
__global__ void prep_w_kernel(const float* __restrict__ base_w,
                              const float* __restrict__ spline_w) {
    const int o = blockIdx.y;
    const int k8 = (blockIdx.x * 256 + threadIdx.x) * 8;
    float v[8];
    if (blockIdx.x == 0) {
        const float4* p = reinterpret_cast<const float4*>(base_w + (size_t)o * I_FEAT + k8);
        float4 a = p[0], b = p[1];
        v[0]=a.x; v[1]=a.y; v[2]=a.z; v[3]=a.w; v[4]=b.x; v[5]=b.y; v[6]=b.z; v[7]=b.w;
    } else {
        const float4* p = reinterpret_cast<const float4*>(
            spline_w + (size_t)o * (I_FEAT * G_KNOT) + (k8 - I_FEAT));
        float4 a = p[0], b = p[1];
        v[0]=0.1f*a.x; v[1]=0.1f*a.y; v[2]=0.1f*a.z; v[3]=0.1f*a.w;
        v[4]=0.1f*b.x; v[5]=0.1f*b.y; v[6]=0.1f*b.z; v[7]=0.1f*b.w;
    }
    Pack8 hi, lo;
    split8(v, hi, lo);
    const size_t idx = (size_t)o * K_EXT + k8;
    *reinterpret_cast<Pack8*>(&g_Bhi[idx]) = hi;
    *reinterpret_cast<Pack8*>(&g_Blo[idx]) = lo;
}

// grid (K_EXT/2048, B_ROWS), 256 thr
__global__ void prep_x_kernel(const float* __restrict__ x,
                              const float* __restrict__ knots) {
    const int b = blockIdx.y;
    const int k8 = (blockIdx.x * 256 + threadIdx.x) * 8;
    float v[8];
    if (blockIdx.x == 0) {
        const float4* p = reinterpret_cast<const float4*>(x + (size_t)b * I_FEAT + k8);
        float4 a = p[0], c = p[1];
        v[0]=a.x; v[1]=a.y; v[2]=a.z; v[3]=a.w; v[4]=c.x; v[5]=c.y; v[6]=c.z; v[7]=c.w;
    } else {
        const int i = (k8 - I_FEAT) >> 3;
        const float xv = __ldg(&x[(size_t)b * I_FEAT + i]);
        const float4 kn0 = *reinterpret_cast<const float4*>(knots);
        const float4 kn1 = *(reinterpret_cast<const float4*>(knots) + 1);
        v[0]=fmaxf(xv-kn0.x,0.f); v[1]=fmaxf(xv-kn0.y,0.f);
        v[2]=fmaxf(xv-kn0.z,0.f); v[3]=fmaxf(xv-kn0.w,0.f);
        v[4]=fmaxf(xv-kn1.x,0.f); v[5]=fmaxf(xv-kn1.y,0.f);
        v[6]=fmaxf(xv-kn1.z,0.f); v[7]=fmaxf(xv-kn1.w,0.f);
    }
    Pack8 hi, lo;
    split8(v, hi, lo);
    const size_t idx = (size_t)b * K_EXT + k8;
    *reinterpret_cast<Pack8*>(&g_Ahi[idx]) = hi;
    *reinterpret_cast<Pack8*>(&g_Alo[idx]) = lo;
}

// ------------------------------ GEMM kernel ---------------------------------
// Stage layout: Ahi @0 (32K), Alo @32768, Bhi @65536 (16K), Blo @81920.

__device__ __forceinline__ void load_chunk(const __nv_bfloat16* gAh,
                                           const __nv_bfloat16* gAl,
                                           const __nv_bfloat16* gBh,
                                           const __nv_bfloat16* gBl,
                                           uint32_t st, int tid) {
    // A matrices: 256 rows x 128B = 2048 16B pieces each
#pragma unroll
    for (int i = 0; i < 8; ++i) {
        const int idx = tid + i * 256;
        const int row = idx >> 3;
        const int sub = idx & 7;
        const uint32_t off = (uint32_t)(row * 128 + sub * 16);
        const uint32_t sw = off ^ ((off >> 3) & 0x70u);
        const size_t gofs = (size_t)row * (K_EXT * 2) + sub * 16;
        CP_ASYNC16(st + sw, reinterpret_cast<const char*>(gAh) + gofs);
        CP_ASYNC16(st + 32768 + sw, reinterpret_cast<const char*>(gAl) + gofs);
    }
    // B matrices: 128 rows x 128B = 1024 pieces each
#pragma unroll
    for (int i = 0; i < 4; ++i) {
        const int idx = tid + i * 256;
        const int row = idx >> 3;
        const int sub = idx & 7;
        const uint32_t off = (uint32_t)(row * 128 + sub * 16);
        const uint32_t sw = off ^ ((off >> 3) & 0x70u);
        const size_t gofs = (size_t)row * (K_EXT * 2) + sub * 16;
        CP_ASYNC16(st + 65536 + sw, reinterpret_cast<const char*>(gBh) + gofs);
        CP_ASYNC16(st + 81920 + sw, reinterpret_cast<const char*>(gBl) + gofs);
    }
}

__global__ void __launch_bounds__(256, 1) kan_gemm(float* __restrict__ out) {
    extern __shared__ char smem[];
    const uint32_t sm0 = smem_to_u32(smem);
    const int tid = threadIdx.x;
    const int lane = tid & 31;
    const int warp = tid >> 5;
    const int wm = warp & 3;       // 4 warps along M (64 rows each)
    const int wn = warp >> 2;      // 2 warps along N (64 cols each)

    // raster swizzle: group 4 m-blocks so a wave's A footprint stays L2-sized
    const int bid = blockIdx.y * gridDim.x + blockIdx.x;   // 0..255
    const int GM = 4;
    const int grp = bid / (GM * 16);
    const int inb = bid % (GM * 16);
    const int m_blk = grp * GM + (inb % GM);
    const int n_blk = inb / GM;

    const size_t m0 = (size_t)m_blk * M_TILE;
    const size_t n0 = (size_t)n_blk * N_TILE;
    const __nv_bfloat16* pAh = g_Ahi + m0 * K_EXT;
    const __nv_bfloat16* pAl = g_Alo + m0 * K_EXT;
    const __nv_bfloat16* pBh = g_Bhi + n0 * K_EXT;
    const __nv_bfloat16* pBl = g_Blo + n0 * K_EXT;

    float acc[4][8][4] = {};

    // ldmatrix lane mappings (x4 = one m16k16 A frag / two n8k16 B frags)
    const int a_lr = (lane & 7) | (((lane >> 3) & 1) << 3);
    const int a_ko = (lane >> 4) << 4;            // +16B for k+8 halves
    const int b_lr = (lane & 7) | (((lane >> 4) & 1) << 3);
    const int b_ko = ((lane >> 3) & 1) << 4;
    const uint32_t xorl = (uint32_t)((lane & 7) << 4);

    uint32_t a_rowoff[4], b_rowoff[4];
#pragma unroll
    for (int mt = 0; mt < 4; ++mt)
        a_rowoff[mt] = (uint32_t)((wm * 64 + mt * 16 + a_lr) * 128);
#pragma unroll
    for (int nt2 = 0; nt2 < 4; ++nt2)
        b_rowoff[nt2] = (uint32_t)((wn * 64 + nt2 * 16 + b_lr) * 128);

    load_chunk(pAh, pAl, pBh, pBl, sm0, tid);
    CP_COMMIT();

    for (int c = 0; c < N_CHUNKS; ++c) {
        if (c + 1 < N_CHUNKS) {
            const int k1 = (c + 1) * K_CHUNK;
            load_chunk(pAh + k1, pAl + k1, pBh + k1, pBl + k1,
                       sm0 + (uint32_t)(((c + 1) & 1) * STAGE_BYTES), tid);
        }
        CP_COMMIT();
        CP_WAIT1();
        __syncthreads();

        const uint32_t sb = sm0 + (uint32_t)((c & 1) * STAGE_BYTES);
#pragma unroll
        for (int ks = 0; ks < 4; ++ks) {
            const uint32_t kb = (uint32_t)(ks * 32);
            uint32_t ah[4][4], al[4][4];
#pragma unroll
            for (int mt = 0; mt < 4; ++mt) {
                const uint32_t ad = sb + a_rowoff[mt] + ((kb + a_ko) ^ xorl);
                LDSM4(ah[mt], ad);
                LDSM4(al[mt], ad + 32768);
            }
            uint32_t bh[4][4], bl[4][4];
#pragma unroll
            for (int nt2 = 0; nt2 < 4; ++nt2) {
                const uint32_t bd = sb + 65536 + b_rowoff[nt2] + ((kb + b_ko) ^ xorl);
                LDSM4(bh[nt2], bd);
                LDSM4(bl[nt2], bd + 16384);
            }
#pragma unroll
            for (int mt = 0; mt < 4; ++mt) {
#pragma unroll
                for (int nt = 0; nt < 8; ++nt) {
                    uint32_t* bH = &bh[nt >> 1][(nt & 1) * 2];
                    uint32_t* bL = &bl[nt >> 1][(nt & 1) * 2];
                    MMA_BF16(acc[mt][nt], ah[mt], bH);   // hi * Hi
                    MMA_BF16(acc[mt][nt], ah[mt], bL);   // hi * Lo
                    MMA_BF16(acc[mt][nt], al[mt], bH);   // lo * Hi
                }
            }
        }
        __syncthreads();
    }

    // Epilogue: direct global stores from accumulators
    const int r = lane >> 2;
    const int cp2 = (lane & 3) * 2;
#pragma unroll
    for (int mt = 0; mt < 4; ++mt) {
        const size_t row = m0 + wm * 64 + mt * 16 + r;
#pragma unroll
        for (int nt = 0; nt < 8; ++nt) {
            const size_t col = n0 + wn * 64 + nt * 8 + cp2;
            *reinterpret_cast<float2*>(&out[row * O_COLS + col]) =
                make_float2(acc[mt][nt][0], acc[mt][nt][1]);
            *reinterpret_cast<float2*>(&out[(row + 8) * O_COLS + col]) =
                make_float2(acc[mt][nt][2], acc[mt][nt][3]);
        }
    }
}

// ------------------------------- launch -------------------------------------

extern "C" void kernel_launch(void* const* d_in, const int* in_sizes, int n_in,
                              void* d_out, int out_size) {
    const float* x        = (const float*)d_in[0];
    const float* base_w   = (const float*)d_in[1];
    const float* spline_w = (const float*)d_in[2];
    const float* knots    = (const float*)d_in[3];
    float* out = (float*)d_out;

    prep_w_kernel<<<dim3(K_EXT / 2048, O_COLS), 256>>>(base_w, spline_w);
    prep_x_kernel<<<dim3(K_EXT / 2048, B_ROWS), 256>>>(x, knots);

    cudaFuncSetAttribute(kan_gemm, cudaFuncAttributeMaxDynamicSharedMemorySize,
                         SMEM_BYTES);
    kan_gemm<<<dim3(O_COLS / N_TILE, B_ROWS / M_TILE), 256, SMEM_BYTES>>>(out);
}

// round 4
// speedup vs baseline: 1.1188x; 1.0101x over previous
#include <cuda_runtime.h>
#include <cuda_fp16.h>
#include <cstdint>
#include <cstddef>

// ---------------------------------------------------------------------------
// KANLayer as one big GEMM (mma.sync fp16, split-fp16 x3 products):
//   out[4096,2048] = X_ext[4096,18432] @ W_ext[2048,18432]^T
// Round 4: fp16 split (calibrates error floor vs amplification), burst-ordered
// inner loop. Same tiling as round 3 (256x128 CTA, 64x64 warp).
// ---------------------------------------------------------------------------

#define B_ROWS 4096
#define O_COLS 2048
#define I_FEAT 2048
#define G_KNOT 8
#define K_EXT  (I_FEAT + I_FEAT * G_KNOT)   // 18432
#define K_CHUNK 64
#define N_CHUNKS (K_EXT / K_CHUNK)           // 288

#define M_TILE 256
#define N_TILE 128
// stage: [Ahi 32K][Alo 32K][Bhi 16K][Blo 16K] = 96KB
#define STAGE_BYTES 98304
#define SMEM_BYTES (2 * STAGE_BYTES)         // 196608

__device__ __half g_Ahi[(size_t)B_ROWS * K_EXT];
__device__ __half g_Alo[(size_t)B_ROWS * K_EXT];
__device__ __half g_Bhi[(size_t)O_COLS * K_EXT];
__device__ __half g_Blo[(size_t)O_COLS * K_EXT];

// ------------------------------ PTX helpers --------------------------------
__device__ __forceinline__ uint32_t smem_to_u32(const void* p) {
    uint32_t a;
    asm("{ .reg .u64 t; cvta.to.shared.u64 t, %1; cvt.u32.u64 %0, t; }"
        : "=r"(a) : "l"(p));
    return a;
}

#define CP_ASYNC16(dst, src) \
    asm volatile("cp.async.cg.shared.global [%0], [%1], 16;" \
                 :: "r"(dst), "l"(src))
#define CP_COMMIT() asm volatile("cp.async.commit_group;" ::: "memory")
#define CP_WAIT1()  asm volatile("cp.async.wait_group 1;" ::: "memory")

#define LDSM4(r, addr) \
    asm volatile("ldmatrix.sync.aligned.m8n8.x4.shared.b16 {%0,%1,%2,%3}, [%4];" \
        : "=r"((r)[0]), "=r"((r)[1]), "=r"((r)[2]), "=r"((r)[3]) : "r"(addr))

#define MMA_F16(d, a, b) \
    asm volatile("mma.sync.aligned.m16n8k16.row.col.f32.f16.f16.f32 " \
        "{%0,%1,%2,%3}, {%4,%5,%6,%7}, {%8,%9}, {%0,%1,%2,%3};" \
        : "+f"((d)[0]), "+f"((d)[1]), "+f"((d)[2]), "+f"((d)[3]) \
        : "r"((a)[0]), "r"((a)[1]), "r"((a)[2]), "r"((a)[3]), \
          "r"((b)[0]), "r"((b)[1]))

// --------------------------- preprocessing kernels --------------------------

struct alignas(16) Pack8 { __half v[8]; };

__device__ __forceinline__ void split8(const float* v, Pack8& hi, Pack8& lo) {
#pragma unroll
    for (int j = 0; j < 8; ++j) {
        __half h = __float2half(v[j]);
        hi.v[j] = h;
        lo.v[j] = __float2half(v[j] - __half2float(h));
    }
}

// grid (K_EXT/2048, O_COLS), 256 thr; thread -> 8 consecutive k
__global__ void prep_w_kernel(const float* __restrict__ base_w,
                              const float* __restrict__ spline_w) {
    const int o = blockIdx.y;
    const int k8 = (blockIdx.x * 256 + threadIdx.x) * 8;
    float v[8];
    if (blockIdx.x == 0) {
        const float4* p = reinterpret_cast<const float4*>(base_w + (size_t)o * I_FEAT + k8);
        float4 a = p[0], b = p[1];
        v[0]=a.x; v[1]=a.y; v[2]=a.z; v[3]=a.w; v[4]=b.x; v[5]=b.y; v[6]=b.z; v[7]=b.w;
    } else {
        const float4* p = reinterpret_cast<const float4*>(
            spline_w + (size_t)o * (I_FEAT * G_KNOT) + (k8 - I_FEAT));
        float4 a = p[0], b = p[1];
        v[0]=0.1f*a.x; v[1]=0.1f*a.y; v[2]=0.1f*a.z; v[3]=0.1f*a.w;
        v[4]=0.1f*b.x; v[5]=0.1f*b.y; v[6]=0.1f*b.z; v[7]=0.1f*b.w;
    }
    Pack8 hi, lo;
    split8(v, hi, lo);
    const size_t idx = (size_t)o * K_EXT + k8;
    *reinterpret_cast<Pack8*>(&g_Bhi[idx]) = hi;
    *reinterpret_cast<Pack8*>(&g_Blo[idx]) = lo;
}

// grid (K_EXT/2048, B_ROWS), 256 thr
__global__ void prep_x_kernel(const float* __restrict__ x,
                              const float* __restrict__ knots) {
    const int b = blockIdx.y;
    const int k8 = (blockIdx.x * 256 + threadIdx.x) * 8;
    float v[8];
    if (blockIdx.x == 0) {
        const float4* p = reinterpret_cast<const float4*>(x + (size_t)b * I_FEAT + k8);
        float4 a = p[0], c = p[1];
        v[0]=a.x; v[1]=a.y; v[2]=a.z; v[3]=a.w; v[4]=c.x; v[5]=c.y; v[6]=c.z; v[7]=c.w;
    } else {
        const int i = (k8 - I_FEAT) >> 3;
        const float xv = __ldg(&x[(size_t)b * I_FEAT + i]);
        const float4 kn0 = *reinterpret_cast<const float4*>(knots);
        const float4 kn1 = *(reinterpret_cast<const float4*>(knots) + 1);
        v[0]=fmaxf(xv-kn0.x,0.f); v[1]=fmaxf(xv-kn0.y,0.f);
        v[2]=fmaxf(xv-kn0.z,0.f); v[3]=fmaxf(xv-kn0.w,0.f);
        v[4]=fmaxf(xv-kn1.x,0.f); v[5]=fmaxf(xv-kn1.y,0.f);
        v[6]=fmaxf(xv-kn1.z,0.f); v[7]=fmaxf(xv-kn1.w,0.f);
    }
    Pack8 hi, lo;
    split8(v, hi, lo);
    const size_t idx = (size_t)b * K_EXT + k8;
    *reinterpret_cast<Pack8*>(&g_Ahi[idx]) = hi;
    *reinterpret_cast<Pack8*>(&g_Alo[idx]) = lo;
}

// ------------------------------ GEMM kernel ---------------------------------
// Stage layout: Ahi @0 (32K), Alo @32768, Bhi @65536 (16K), Blo @81920.

__device__ __forceinline__ void load_chunk(const __half* gAh,
                                           const __half* gAl,
                                           const __half* gBh,
                                           const __half* gBl,
                                           uint32_t st, int tid) {
#pragma unroll
    for (int i = 0; i < 8; ++i) {
        const int idx = tid + i * 256;
        const int row = idx >> 3;
        const int sub = idx & 7;
        const uint32_t off = (uint32_t)(row * 128 + sub * 16);
        const uint32_t sw = off ^ ((off >> 3) & 0x70u);
        const size_t gofs = (size_t)row * (K_EXT * 2) + sub * 16;
        CP_ASYNC16(st + sw, reinterpret_cast<const char*>(gAh) + gofs);
        CP_ASYNC16(st + 32768 + sw, reinterpret_cast<const char*>(gAl) + gofs);
    }
#pragma unroll
    for (int i = 0; i < 4; ++i) {
        const int idx = tid + i * 256;
        const int row = idx >> 3;
        const int sub = idx & 7;
        const uint32_t off = (uint32_t)(row * 128 + sub * 16);
        const uint32_t sw = off ^ ((off >> 3) & 0x70u);
        const size_t gofs = (size_t)row * (K_EXT * 2) + sub * 16;
        CP_ASYNC16(st + 65536 + sw, reinterpret_cast<const char*>(gBh) + gofs);
        CP_ASYNC16(st + 81920 + sw, reinterpret_cast<const char*>(gBl) + gofs);
    }
}

__global__ void __launch_bounds__(256, 1) kan_gemm(float* __restrict__ out) {
    extern __shared__ char smem[];
    const uint32_t sm0 = smem_to_u32(smem);
    const int tid = threadIdx.x;
    const int lane = tid & 31;
    const int warp = tid >> 5;
    const int wm = warp & 3;       // 4 warps along M (64 rows each)
    const int wn = warp >> 2;      // 2 warps along N (64 cols each)

    const int bid = blockIdx.y * gridDim.x + blockIdx.x;   // 0..255
    const int GM = 4;
    const int grp = bid / (GM * 16);
    const int inb = bid % (GM * 16);
    const int m_blk = grp * GM + (inb % GM);
    const int n_blk = inb / GM;

    const size_t m0 = (size_t)m_blk * M_TILE;
    const size_t n0 = (size_t)n_blk * N_TILE;
    const __half* pAh = g_Ahi + m0 * K_EXT;
    const __half* pAl = g_Alo + m0 * K_EXT;
    const __half* pBh = g_Bhi + n0 * K_EXT;
    const __half* pBl = g_Blo + n0 * K_EXT;

    float acc[4][8][4] = {};

    const int a_lr = (lane & 7) | (((lane >> 3) & 1) << 3);
    const int a_ko = (lane >> 4) << 4;
    const int b_lr = (lane & 7) | (((lane >> 4) & 1) << 3);
    const int b_ko = ((lane >> 3) & 1) << 4;
    const uint32_t xorl = (uint32_t)((lane & 7) << 4);

    uint32_t a_rowoff[4], b_rowoff[4];
#pragma unroll
    for (int mt = 0; mt < 4; ++mt)
        a_rowoff[mt] = (uint32_t)((wm * 64 + mt * 16 + a_lr) * 128);
#pragma unroll
    for (int nt2 = 0; nt2 < 4; ++nt2)
        b_rowoff[nt2] = (uint32_t)((wn * 64 + nt2 * 16 + b_lr) * 128);

    load_chunk(pAh, pAl, pBh, pBl, sm0, tid);
    CP_COMMIT();

    for (int c = 0; c < N_CHUNKS; ++c) {
        if (c + 1 < N_CHUNKS) {
            const int k1 = (c + 1) * K_CHUNK;
            load_chunk(pAh + k1, pAl + k1, pBh + k1, pBl + k1,
                       sm0 + (uint32_t)(((c + 1) & 1) * STAGE_BYTES), tid);
        }
        CP_COMMIT();
        CP_WAIT1();
        __syncthreads();

        const uint32_t sb = sm0 + (uint32_t)((c & 1) * STAGE_BYTES);
#pragma unroll
        for (int ks = 0; ks < 4; ++ks) {
            const uint32_t kb = (uint32_t)(ks * 32);
            const uint32_t kA = (kb + a_ko) ^ xorl;
            const uint32_t kB = (kb + b_ko) ^ xorl;

            // --- phase 1: hi*Hi ---
            uint32_t ah[4][4], bh[4][4];
#pragma unroll
            for (int mt = 0; mt < 4; ++mt) LDSM4(ah[mt], sb + a_rowoff[mt] + kA);
#pragma unroll
            for (int nt2 = 0; nt2 < 4; ++nt2)
                LDSM4(bh[nt2], sb + 65536 + b_rowoff[nt2] + kB);
#pragma unroll
            for (int mt = 0; mt < 4; ++mt)
#pragma unroll
                for (int nt = 0; nt < 8; ++nt)
                    MMA_F16(acc[mt][nt], ah[mt], &bh[nt >> 1][(nt & 1) * 2]);

            // --- phase 2: lo*Hi ---
            uint32_t al[4][4];
#pragma unroll
            for (int mt = 0; mt < 4; ++mt)
                LDSM4(al[mt], sb + 32768 + a_rowoff[mt] + kA);
#pragma unroll
            for (int mt = 0; mt < 4; ++mt)
#pragma unroll
                for (int nt = 0; nt < 8; ++nt)
                    MMA_F16(acc[mt][nt], al[mt], &bh[nt >> 1][(nt & 1) * 2]);

            // --- phase 3: hi*Lo ---
            uint32_t bl[4][4];
#pragma unroll
            for (int nt2 = 0; nt2 < 4; ++nt2)
                LDSM4(bl[nt2], sb + 81920 + b_rowoff[nt2] + kB);
#pragma unroll
            for (int mt = 0; mt < 4; ++mt)
#pragma unroll
                for (int nt = 0; nt < 8; ++nt)
                    MMA_F16(acc[mt][nt], ah[mt], &bl[nt >> 1][(nt & 1) * 2]);
        }
        __syncthreads();
    }

    // Epilogue: direct global stores from accumulators
    const int r = lane >> 2;
    const int cp2 = (lane & 3) * 2;
#pragma unroll
    for (int mt = 0; mt < 4; ++mt) {
        const size_t row = m0 + wm * 64 + mt * 16 + r;
#pragma unroll
        for (int nt = 0; nt < 8; ++nt) {
            const size_t col = n0 + wn * 64 + nt * 8 + cp2;
            *reinterpret_cast<float2*>(&out[row * O_COLS + col]) =
                make_float2(acc[mt][nt][0], acc[mt][nt][1]);
            *reinterpret_cast<float2*>(&out[(row + 8) * O_COLS + col]) =
                make_float2(acc[mt][nt][2], acc[mt][nt][3]);
        }
    }
}

// ------------------------------- launch -------------------------------------

extern "C" void kernel_launch(void* const* d_in, const int* in_sizes, int n_in,
                              void* d_out, int out_size) {
    const float* x        = (const float*)d_in[0];
    const float* base_w   = (const float*)d_in[1];
    const float* spline_w = (const float*)d_in[2];
    const float* knots    = (const float*)d_in[3];
    float* out = (float*)d_out;

    prep_w_kernel<<<dim3(K_EXT / 2048, O_COLS), 256>>>(base_w, spline_w);
    prep_x_kernel<<<dim3(K_EXT / 2048, B_ROWS), 256>>>(x, knots);

    cudaFuncSetAttribute(kan_gemm, cudaFuncAttributeMaxDynamicSharedMemorySize,
                         SMEM_BYTES);
    kan_gemm<<<dim3(O_COLS / N_TILE, B_ROWS / M_TILE), 256, SMEM_BYTES>>>(out);
}

// round 5
// speedup vs baseline: 2.8485x; 2.5460x over previous
#include <cuda_runtime.h>
#include <cuda_fp16.h>
#include <cstdint>
#include <cstddef>

// ---------------------------------------------------------------------------
// KANLayer as one big GEMM (mma.sync fp16, SINGLE product):
//   out[4096,2048] = X_ext[4096,18432] @ W_ext[2048,18432]^T
// Round 5: error floor (~6.8e-5) shown independent of split scheme ->
// drop to 1 fp16 product (3x fewer HMMA). Tile 256x128, warp 64x64.
// ---------------------------------------------------------------------------

#define B_ROWS 4096
#define O_COLS 2048
#define I_FEAT 2048
#define G_KNOT 8
#define K_EXT  (I_FEAT + I_FEAT * G_KNOT)   // 18432
#define K_CHUNK 64
#define N_CHUNKS (K_EXT / K_CHUNK)           // 288

#define M_TILE 256
#define N_TILE 128
// stage: [A 32K][B 16K] = 48KB
#define STAGE_BYTES 49152
#define SMEM_BYTES (2 * STAGE_BYTES)         // 98304

__device__ __half g_A[(size_t)B_ROWS * K_EXT];
__device__ __half g_B[(size_t)O_COLS * K_EXT];

// ------------------------------ PTX helpers --------------------------------
__device__ __forceinline__ uint32_t smem_to_u32(const void* p) {
    uint32_t a;
    asm("{ .reg .u64 t; cvta.to.shared.u64 t, %1; cvt.u32.u64 %0, t; }"
        : "=r"(a) : "l"(p));
    return a;
}

#define CP_ASYNC16(dst, src) \
    asm volatile("cp.async.cg.shared.global [%0], [%1], 16;" \
                 :: "r"(dst), "l"(src))
#define CP_COMMIT() asm volatile("cp.async.commit_group;" ::: "memory")
#define CP_WAIT1()  asm volatile("cp.async.wait_group 1;" ::: "memory")

#define LDSM4(r, addr) \
    asm volatile("ldmatrix.sync.aligned.m8n8.x4.shared.b16 {%0,%1,%2,%3}, [%4];" \
        : "=r"((r)[0]), "=r"((r)[1]), "=r"((r)[2]), "=r"((r)[3]) : "r"(addr))

#define MMA_F16(d, a, b) \
    asm volatile("mma.sync.aligned.m16n8k16.row.col.f32.f16.f16.f32 " \
        "{%0,%1,%2,%3}, {%4,%5,%6,%7}, {%8,%9}, {%0,%1,%2,%3};" \
        : "+f"((d)[0]), "+f"((d)[1]), "+f"((d)[2]), "+f"((d)[3]) \
        : "r"((a)[0]), "r"((a)[1]), "r"((a)[2]), "r"((a)[3]), \
          "r"((b)[0]), "r"((b)[1]))

// --------------------------- preprocessing kernels --------------------------

struct alignas(16) Pack8 { __half v[8]; };

// grid (K_EXT/2048, O_COLS), 256 thr; thread -> 8 consecutive k
__global__ void prep_w_kernel(const float* __restrict__ base_w,
                              const float* __restrict__ spline_w) {
    const int o = blockIdx.y;
    const int k8 = (blockIdx.x * 256 + threadIdx.x) * 8;
    float v[8];
    if (blockIdx.x == 0) {
        const float4* p = reinterpret_cast<const float4*>(base_w + (size_t)o * I_FEAT + k8);
        float4 a = p[0], b = p[1];
        v[0]=a.x; v[1]=a.y; v[2]=a.z; v[3]=a.w; v[4]=b.x; v[5]=b.y; v[6]=b.z; v[7]=b.w;
    } else {
        const float4* p = reinterpret_cast<const float4*>(
            spline_w + (size_t)o * (I_FEAT * G_KNOT) + (k8 - I_FEAT));
        float4 a = p[0], b = p[1];
        v[0]=0.1f*a.x; v[1]=0.1f*a.y; v[2]=0.1f*a.z; v[3]=0.1f*a.w;
        v[4]=0.1f*b.x; v[5]=0.1f*b.y; v[6]=0.1f*b.z; v[7]=0.1f*b.w;
    }
    Pack8 h;
#pragma unroll
    for (int j = 0; j < 8; ++j) h.v[j] = __float2half(v[j]);
    *reinterpret_cast<Pack8*>(&g_B[(size_t)o * K_EXT + k8]) = h;
}

// grid (K_EXT/2048, B_ROWS), 256 thr
__global__ void prep_x_kernel(const float* __restrict__ x,
                              const float* __restrict__ knots) {
    const int b = blockIdx.y;
    const int k8 = (blockIdx.x * 256 + threadIdx.x) * 8;
    float v[8];
    if (blockIdx.x == 0) {
        const float4* p = reinterpret_cast<const float4*>(x + (size_t)b * I_FEAT + k8);
        float4 a = p[0], c = p[1];
        v[0]=a.x; v[1]=a.y; v[2]=a.z; v[3]=a.w; v[4]=c.x; v[5]=c.y; v[6]=c.z; v[7]=c.w;
    } else {
        const int i = (k8 - I_FEAT) >> 3;
        const float xv = __ldg(&x[(size_t)b * I_FEAT + i]);
        const float4 kn0 = *reinterpret_cast<const float4*>(knots);
        const float4 kn1 = *(reinterpret_cast<const float4*>(knots) + 1);
        v[0]=fmaxf(xv-kn0.x,0.f); v[1]=fmaxf(xv-kn0.y,0.f);
        v[2]=fmaxf(xv-kn0.z,0.f); v[3]=fmaxf(xv-kn0.w,0.f);
        v[4]=fmaxf(xv-kn1.x,0.f); v[5]=fmaxf(xv-kn1.y,0.f);
        v[6]=fmaxf(xv-kn1.z,0.f); v[7]=fmaxf(xv-kn1.w,0.f);
    }
    Pack8 h;
#pragma unroll
    for (int j = 0; j < 8; ++j) h.v[j] = __float2half(v[j]);
    *reinterpret_cast<Pack8*>(&g_A[(size_t)b * K_EXT + k8]) = h;
}

// ------------------------------ GEMM kernel ---------------------------------
// Stage layout: A @0 (32K), B @32768 (16K). SW128 XOR swizzle.

__device__ __forceinline__ void load_chunk(const __half* gA, const __half* gB,
                                           uint32_t st, int tid) {
#pragma unroll
    for (int i = 0; i < 8; ++i) {           // A: 256 rows x 128B
        const int idx = tid + i * 256;
        const int row = idx >> 3;
        const int sub = idx & 7;
        const uint32_t off = (uint32_t)(row * 128 + sub * 16);
        const uint32_t sw = off ^ ((off >> 3) & 0x70u);
        CP_ASYNC16(st + sw,
                   reinterpret_cast<const char*>(gA) + (size_t)row * (K_EXT * 2) + sub * 16);
    }
#pragma unroll
    for (int i = 0; i < 4; ++i) {           // B: 128 rows x 128B
        const int idx = tid + i * 256;
        const int row = idx >> 3;
        const int sub = idx & 7;
        const uint32_t off = (uint32_t)(row * 128 + sub * 16);
        const uint32_t sw = off ^ ((off >> 3) & 0x70u);
        CP_ASYNC16(st + 32768 + sw,
                   reinterpret_cast<const char*>(gB) + (size_t)row * (K_EXT * 2) + sub * 16);
    }
}

__global__ void __launch_bounds__(256, 1) kan_gemm(float* __restrict__ out) {
    extern __shared__ char smem[];
    const uint32_t sm0 = smem_to_u32(smem);
    const int tid = threadIdx.x;
    const int lane = tid & 31;
    const int warp = tid >> 5;
    const int wm = warp & 3;       // 4 warps along M (64 rows each)
    const int wn = warp >> 2;      // 2 warps along N (64 cols each)

    // raster swizzle: groups of 4 m-blocks x all 16 n-blocks
    const int bid = blockIdx.y * gridDim.x + blockIdx.x;   // 0..255
    const int GM = 4;
    const int grp = bid / (GM * 16);
    const int inb = bid % (GM * 16);
    const int m_blk = grp * GM + (inb % GM);
    const int n_blk = inb / GM;

    const size_t m0 = (size_t)m_blk * M_TILE;
    const size_t n0 = (size_t)n_blk * N_TILE;
    const __half* pA = g_A + m0 * K_EXT;
    const __half* pB = g_B + n0 * K_EXT;

    float acc[4][8][4] = {};

    const int a_lr = (lane & 7) | (((lane >> 3) & 1) << 3);
    const int a_ko = (lane >> 4) << 4;
    const int b_lr = (lane & 7) | (((lane >> 4) & 1) << 3);
    const int b_ko = ((lane >> 3) & 1) << 4;
    const uint32_t xorl = (uint32_t)((lane & 7) << 4);

    uint32_t a_rowoff[4], b_rowoff[4];
#pragma unroll
    for (int mt = 0; mt < 4; ++mt)
        a_rowoff[mt] = (uint32_t)((wm * 64 + mt * 16 + a_lr) * 128);
#pragma unroll
    for (int nt2 = 0; nt2 < 4; ++nt2)
        b_rowoff[nt2] = (uint32_t)((wn * 64 + nt2 * 16 + b_lr) * 128);

    load_chunk(pA, pB, sm0, tid);
    CP_COMMIT();

    for (int c = 0; c < N_CHUNKS; ++c) {
        if (c + 1 < N_CHUNKS) {
            const int k1 = (c + 1) * K_CHUNK;
            load_chunk(pA + k1, pB + k1,
                       sm0 + (uint32_t)(((c + 1) & 1) * STAGE_BYTES), tid);
        }
        CP_COMMIT();
        CP_WAIT1();
        __syncthreads();

        const uint32_t sb = sm0 + (uint32_t)((c & 1) * STAGE_BYTES);
#pragma unroll
        for (int ks = 0; ks < 4; ++ks) {
            const uint32_t kb = (uint32_t)(ks * 32);
            const uint32_t kA = (kb + a_ko) ^ xorl;
            const uint32_t kB = (kb + b_ko) ^ xorl;

            uint32_t ah[4][4], bh[4][4];
#pragma unroll
            for (int mt = 0; mt < 4; ++mt) LDSM4(ah[mt], sb + a_rowoff[mt] + kA);
#pragma unroll
            for (int nt2 = 0; nt2 < 4; ++nt2)
                LDSM4(bh[nt2], sb + 32768 + b_rowoff[nt2] + kB);
#pragma unroll
            for (int mt = 0; mt < 4; ++mt)
#pragma unroll
                for (int nt = 0; nt < 8; ++nt)
                    MMA_F16(acc[mt][nt], ah[mt], &bh[nt >> 1][(nt & 1) * 2]);
        }
        __syncthreads();
    }

    // Epilogue: direct global stores from accumulators
    const int r = lane >> 2;
    const int cp2 = (lane & 3) * 2;
#pragma unroll
    for (int mt = 0; mt < 4; ++mt) {
        const size_t row = m0 + wm * 64 + mt * 16 + r;
#pragma unroll
        for (int nt = 0; nt < 8; ++nt) {
            const size_t col = n0 + wn * 64 + nt * 8 + cp2;
            *reinterpret_cast<float2*>(&out[row * O_COLS + col]) =
                make_float2(acc[mt][nt][0], acc[mt][nt][1]);
            *reinterpret_cast<float2*>(&out[(row + 8) * O_COLS + col]) =
                make_float2(acc[mt][nt][2], acc[mt][nt][3]);
        }
    }
}

// ------------------------------- launch -------------------------------------

extern "C" void kernel_launch(void* const* d_in, const int* in_sizes, int n_in,
                              void* d_out, int out_size) {
    const float* x        = (const float*)d_in[0];
    const float* base_w   = (const float*)d_in[1];
    const float* spline_w = (const float*)d_in[2];
    const float* knots    = (const float*)d_in[3];
    float* out = (float*)d_out;

    prep_w_kernel<<<dim3(K_EXT / 2048, O_COLS), 256>>>(base_w, spline_w);
    prep_x_kernel<<<dim3(K_EXT / 2048, B_ROWS), 256>>>(x, knots);

    cudaFuncSetAttribute(kan_gemm, cudaFuncAttributeMaxDynamicSharedMemorySize,
                         SMEM_BYTES);
    kan_gemm<<<dim3(O_COLS / N_TILE, B_ROWS / M_TILE), 256, SMEM_BYTES>>>(out);
}

// round 6
// speedup vs baseline: 2.9841x; 1.0476x over previous
#include <cuda_runtime.h>
#include <cuda_fp16.h>
#include <cstdint>
#include <cstddef>

// ---------------------------------------------------------------------------
// KANLayer as one big GEMM (mma.sync fp16, single product):
//   out[4096,2048] = X_ext[4096,18432] @ W_ext[2048,18432]^T
// Round 6: K_CHUNK=128 (half the sync/wait overhead), explicit LDSM fragment
// double-buffering to overlap smem reads with MMA bursts.
// Tile 256x128, warp 64x64, 2-stage cp.async pipeline.
// ---------------------------------------------------------------------------

#define B_ROWS 4096
#define O_COLS 2048
#define I_FEAT 2048
#define G_KNOT 8
#define K_EXT  (I_FEAT + I_FEAT * G_KNOT)   // 18432
#define K_CHUNK 128
#define N_CHUNKS (K_EXT / K_CHUNK)           // 144

#define M_TILE 256
#define N_TILE 128
// stage: [A0 32K][A1 32K][B0 16K][B1 16K] = 96KB (two 64-wide k-halves)
#define STAGE_BYTES 98304
#define SMEM_BYTES (2 * STAGE_BYTES)         // 196608

__device__ __half g_A[(size_t)B_ROWS * K_EXT];
__device__ __half g_B[(size_t)O_COLS * K_EXT];

// ------------------------------ PTX helpers --------------------------------
__device__ __forceinline__ uint32_t smem_to_u32(const void* p) {
    uint32_t a;
    asm("{ .reg .u64 t; cvta.to.shared.u64 t, %1; cvt.u32.u64 %0, t; }"
        : "=r"(a) : "l"(p));
    return a;
}

#define CP_ASYNC16(dst, src) \
    asm volatile("cp.async.cg.shared.global [%0], [%1], 16;" \
                 :: "r"(dst), "l"(src))
#define CP_COMMIT() asm volatile("cp.async.commit_group;" ::: "memory")
#define CP_WAIT1()  asm volatile("cp.async.wait_group 1;" ::: "memory")

#define LDSM4(r, addr) \
    asm volatile("ldmatrix.sync.aligned.m8n8.x4.shared.b16 {%0,%1,%2,%3}, [%4];" \
        : "=r"((r)[0]), "=r"((r)[1]), "=r"((r)[2]), "=r"((r)[3]) : "r"(addr))

#define MMA_F16(d, a, b) \
    asm volatile("mma.sync.aligned.m16n8k16.row.col.f32.f16.f16.f32 " \
        "{%0,%1,%2,%3}, {%4,%5,%6,%7}, {%8,%9}, {%0,%1,%2,%3};" \
        : "+f"((d)[0]), "+f"((d)[1]), "+f"((d)[2]), "+f"((d)[3]) \
        : "r"((a)[0]), "r"((a)[1]), "r"((a)[2]), "r"((a)[3]), \
          "r"((b)[0]), "r"((b)[1]))

// --------------------------- preprocessing kernels --------------------------

struct alignas(16) Pack8 { __half v[8]; };

// grid (K_EXT/2048, O_COLS), 256 thr; thread -> 8 consecutive k
__global__ void prep_w_kernel(const float* __restrict__ base_w,
                              const float* __restrict__ spline_w) {
    const int o = blockIdx.y;
    const int k8 = (blockIdx.x * 256 + threadIdx.x) * 8;
    float v[8];
    if (blockIdx.x == 0) {
        const float4* p = reinterpret_cast<const float4*>(base_w + (size_t)o * I_FEAT + k8);
        float4 a = p[0], b = p[1];
        v[0]=a.x; v[1]=a.y; v[2]=a.z; v[3]=a.w; v[4]=b.x; v[5]=b.y; v[6]=b.z; v[7]=b.w;
    } else {
        const float4* p = reinterpret_cast<const float4*>(
            spline_w + (size_t)o * (I_FEAT * G_KNOT) + (k8 - I_FEAT));
        float4 a = p[0], b = p[1];
        v[0]=0.1f*a.x; v[1]=0.1f*a.y; v[2]=0.1f*a.z; v[3]=0.1f*a.w;
        v[4]=0.1f*b.x; v[5]=0.1f*b.y; v[6]=0.1f*b.z; v[7]=0.1f*b.w;
    }
    Pack8 h;
#pragma unroll
    for (int j = 0; j < 8; ++j) h.v[j] = __float2half(v[j]);
    *reinterpret_cast<Pack8*>(&g_B[(size_t)o * K_EXT + k8]) = h;
}

// grid (K_EXT/2048, B_ROWS), 256 thr
__global__ void prep_x_kernel(const float* __restrict__ x,
                              const float* __restrict__ knots) {
    const int b = blockIdx.y;
    const int k8 = (blockIdx.x * 256 + threadIdx.x) * 8;
    float v[8];
    if (blockIdx.x == 0) {
        const float4* p = reinterpret_cast<const float4*>(x + (size_t)b * I_FEAT + k8);
        float4 a = p[0], c = p[1];
        v[0]=a.x; v[1]=a.y; v[2]=a.z; v[3]=a.w; v[4]=c.x; v[5]=c.y; v[6]=c.z; v[7]=c.w;
    } else {
        const int i = (k8 - I_FEAT) >> 3;
        const float xv = __ldg(&x[(size_t)b * I_FEAT + i]);
        const float4 kn0 = *reinterpret_cast<const float4*>(knots);
        const float4 kn1 = *(reinterpret_cast<const float4*>(knots) + 1);
        v[0]=fmaxf(xv-kn0.x,0.f); v[1]=fmaxf(xv-kn0.y,0.f);
        v[2]=fmaxf(xv-kn0.z,0.f); v[3]=fmaxf(xv-kn0.w,0.f);
        v[4]=fmaxf(xv-kn1.x,0.f); v[5]=fmaxf(xv-kn1.y,0.f);
        v[6]=fmaxf(xv-kn1.z,0.f); v[7]=fmaxf(xv-kn1.w,0.f);
    }
    Pack8 h;
#pragma unroll
    for (int j = 0; j < 8; ++j) h.v[j] = __float2half(v[j]);
    *reinterpret_cast<Pack8*>(&g_A[(size_t)b * K_EXT + k8]) = h;
}

// ------------------------------ GEMM kernel ---------------------------------
// Stage layout (96KB): A0 @0, A1 @32768, B0 @65536, B1 @81920.
// Each half holds 64 k-columns (128B rows) with SW128 XOR swizzle.

__device__ __forceinline__ void load_chunk(const __half* gA, const __half* gB,
                                           uint32_t st, int tid) {
#pragma unroll
    for (int h = 0; h < 2; ++h) {
        // A: 256 rows x 128B per half
#pragma unroll
        for (int i = 0; i < 8; ++i) {
            const int idx = tid + i * 256;
            const int row = idx >> 3;
            const int sub = idx & 7;
            const uint32_t off = (uint32_t)(row * 128 + sub * 16);
            const uint32_t sw = off ^ ((off >> 3) & 0x70u);
            CP_ASYNC16(st + h * 32768 + sw,
                       reinterpret_cast<const char*>(gA) +
                           (size_t)row * (K_EXT * 2) + h * 128 + sub * 16);
        }
        // B: 128 rows x 128B per half
#pragma unroll
        for (int i = 0; i < 4; ++i) {
            const int idx = tid + i * 256;
            const int row = idx >> 3;
            const int sub = idx & 7;
            const uint32_t off = (uint32_t)(row * 128 + sub * 16);
            const uint32_t sw = off ^ ((off >> 3) & 0x70u);
            CP_ASYNC16(st + 65536 + h * 16384 + sw,
                       reinterpret_cast<const char*>(gB) +
                           (size_t)row * (K_EXT * 2) + h * 128 + sub * 16);
        }
    }
}

__global__ void __launch_bounds__(256, 1) kan_gemm(float* __restrict__ out) {
    extern __shared__ char smem[];
    const uint32_t sm0 = smem_to_u32(smem);
    const int tid = threadIdx.x;
    const int lane = tid & 31;
    const int warp = tid >> 5;
    const int wm = warp & 3;       // 4 warps along M (64 rows each)
    const int wn = warp >> 2;      // 2 warps along N (64 cols each)

    // raster swizzle: groups of 4 m-blocks x all 16 n-blocks
    const int bid = blockIdx.y * gridDim.x + blockIdx.x;   // 0..255
    const int GM = 4;
    const int grp = bid / (GM * 16);
    const int inb = bid % (GM * 16);
    const int m_blk = grp * GM + (inb % GM);
    const int n_blk = inb / GM;

    const size_t m0 = (size_t)m_blk * M_TILE;
    const size_t n0 = (size_t)n_blk * N_TILE;
    const __half* pA = g_A + m0 * K_EXT;
    const __half* pB = g_B + n0 * K_EXT;

    float acc[4][8][4] = {};

    const int a_lr = (lane & 7) | (((lane >> 3) & 1) << 3);
    const int a_ko = (lane >> 4) << 4;
    const int b_lr = (lane & 7) | (((lane >> 4) & 1) << 3);
    const int b_ko = ((lane >> 3) & 1) << 4;
    const uint32_t xorl = (uint32_t)((lane & 7) << 4);

    uint32_t a_rowoff[4], b_rowoff[4];
#pragma unroll
    for (int mt = 0; mt < 4; ++mt)
        a_rowoff[mt] = (uint32_t)((wm * 64 + mt * 16 + a_lr) * 128);
#pragma unroll
    for (int nt2 = 0; nt2 < 4; ++nt2)
        b_rowoff[nt2] = (uint32_t)((wn * 64 + nt2 * 16 + b_lr) * 128);

    load_chunk(pA, pB, sm0, tid);
    CP_COMMIT();

    for (int c = 0; c < N_CHUNKS; ++c) {
        if (c + 1 < N_CHUNKS) {
            const int k1 = (c + 1) * K_CHUNK;
            load_chunk(pA + k1, pB + k1,
                       sm0 + (uint32_t)(((c + 1) & 1) * STAGE_BYTES), tid);
        }
        CP_COMMIT();
        CP_WAIT1();
        __syncthreads();

        const uint32_t sb = sm0 + (uint32_t)((c & 1) * STAGE_BYTES);

        // fragment double buffer over 8 k-steps (two 64-wide halves x 4 steps)
        uint32_t ah[2][4][4], bh[2][4][4];

#define LOAD_FRAGS(ks, buf)                                                    \
        do {                                                                   \
            const uint32_t _ha = (uint32_t)(((ks) >> 2) * 32768);              \
            const uint32_t _hb = (uint32_t)(((ks) >> 2) * 16384);              \
            const uint32_t _kb = (uint32_t)(((ks) & 3) * 32);                  \
            const uint32_t _kA = (_kb + a_ko) ^ xorl;                          \
            const uint32_t _kB = (_kb + b_ko) ^ xorl;                          \
            _Pragma("unroll")                                                  \
            for (int _mt = 0; _mt < 4; ++_mt)                                  \
                LDSM4(ah[buf][_mt], sb + _ha + a_rowoff[_mt] + _kA);           \
            _Pragma("unroll")                                                  \
            for (int _nt = 0; _nt < 4; ++_nt)                                  \
                LDSM4(bh[buf][_nt], sb + 65536 + _hb + b_rowoff[_nt] + _kB);   \
        } while (0)

        LOAD_FRAGS(0, 0);
#pragma unroll
        for (int ks = 0; ks < 8; ++ks) {
            if (ks < 7) LOAD_FRAGS(ks + 1, (ks + 1) & 1);
            const int cur = ks & 1;
#pragma unroll
            for (int mt = 0; mt < 4; ++mt)
#pragma unroll
                for (int nt = 0; nt < 8; ++nt)
                    MMA_F16(acc[mt][nt], ah[cur][mt],
                            &bh[cur][nt >> 1][(nt & 1) * 2]);
        }
#undef LOAD_FRAGS
        __syncthreads();
    }

    // Epilogue: direct global stores from accumulators
    const int r = lane >> 2;
    const int cp2 = (lane & 3) * 2;
#pragma unroll
    for (int mt = 0; mt < 4; ++mt) {
        const size_t row = m0 + wm * 64 + mt * 16 + r;
#pragma unroll
        for (int nt = 0; nt < 8; ++nt) {
            const size_t col = n0 + wn * 64 + nt * 8 + cp2;
            *reinterpret_cast<float2*>(&out[row * O_COLS + col]) =
                make_float2(acc[mt][nt][0], acc[mt][nt][1]);
            *reinterpret_cast<float2*>(&out[(row + 8) * O_COLS + col]) =
                make_float2(acc[mt][nt][2], acc[mt][nt][3]);
        }
    }
}

// ------------------------------- launch -------------------------------------

extern "C" void kernel_launch(void* const* d_in, const int* in_sizes, int n_in,
                              void* d_out, int out_size) {
    const float* x        = (const float*)d_in[0];
    const float* base_w   = (const float*)d_in[1];
    const float* spline_w = (const float*)d_in[2];
    const float* knots    = (const float*)d_in[3];
    float* out = (float*)d_out;

    prep_w_kernel<<<dim3(K_EXT / 2048, O_COLS), 256>>>(base_w, spline_w);
    prep_x_kernel<<<dim3(K_EXT / 2048, B_ROWS), 256>>>(x, knots);

    cudaFuncSetAttribute(kan_gemm, cudaFuncAttributeMaxDynamicSharedMemorySize,
                         SMEM_BYTES);
    kan_gemm<<<dim3(O_COLS / N_TILE, B_ROWS / M_TILE), 256, SMEM_BYTES>>>(out);
}

// round 7
// speedup vs baseline: 3.1576x; 1.0581x over previous
#include <cuda_runtime.h>
#include <cuda_fp16.h>
#include <cstdint>
#include <cstddef>

// ---------------------------------------------------------------------------
// KANLayer as one big GEMM (mma.sync fp16, single product):
//   out[4096,2048] = X_ext[4096,18432] @ W_ext[2048,18432]^T
// Round 7: wave-balancing. 256 output tiles (256x128) -> 148 full tiles
// (1 wave, 1 CTA/SM) + 108 tiles split into 432 quarter-tiles (128x64,
// 2 CTAs/SM). Deterministic, no atomics. K_CHUNK=128, fragment double buffer.
// ---------------------------------------------------------------------------

#define B_ROWS 4096
#define O_COLS 2048
#define I_FEAT 2048
#define G_KNOT 8
#define K_EXT  (I_FEAT + I_FEAT * G_KNOT)   // 18432
#define K_CHUNK 128
#define N_CHUNKS (K_EXT / K_CHUNK)           // 144

#define N_FULL 148                           // tiles done as full 256x128

__device__ __half g_A[(size_t)B_ROWS * K_EXT];
__device__ __half g_B[(size_t)O_COLS * K_EXT];

// ------------------------------ PTX helpers --------------------------------
__device__ __forceinline__ uint32_t smem_to_u32(const void* p) {
    uint32_t a;
    asm("{ .reg .u64 t; cvta.to.shared.u64 t, %1; cvt.u32.u64 %0, t; }"
        : "=r"(a) : "l"(p));
    return a;
}

#define CP_ASYNC16(dst, src) \
    asm volatile("cp.async.cg.shared.global [%0], [%1], 16;" \
                 :: "r"(dst), "l"(src))
#define CP_COMMIT() asm volatile("cp.async.commit_group;" ::: "memory")
#define CP_WAIT1()  asm volatile("cp.async.wait_group 1;" ::: "memory")

#define LDSM4(r, addr) \
    asm volatile("ldmatrix.sync.aligned.m8n8.x4.shared.b16 {%0,%1,%2,%3}, [%4];" \
        : "=r"((r)[0]), "=r"((r)[1]), "=r"((r)[2]), "=r"((r)[3]) : "r"(addr))

#define MMA_F16(d, a, b) \
    asm volatile("mma.sync.aligned.m16n8k16.row.col.f32.f16.f16.f32 " \
        "{%0,%1,%2,%3}, {%4,%5,%6,%7}, {%8,%9}, {%0,%1,%2,%3};" \
        : "+f"((d)[0]), "+f"((d)[1]), "+f"((d)[2]), "+f"((d)[3]) \
        : "r"((a)[0]), "r"((a)[1]), "r"((a)[2]), "r"((a)[3]), \
          "r"((b)[0]), "r"((b)[1]))

// --------------------------- preprocessing kernels --------------------------

struct alignas(16) Pack8 { __half v[8]; };

// grid (K_EXT/2048, O_COLS), 256 thr; thread -> 8 consecutive k
__global__ void prep_w_kernel(const float* __restrict__ base_w,
                              const float* __restrict__ spline_w) {
    const int o = blockIdx.y;
    const int k8 = (blockIdx.x * 256 + threadIdx.x) * 8;
    float v[8];
    if (blockIdx.x == 0) {
        const float4* p = reinterpret_cast<const float4*>(base_w + (size_t)o * I_FEAT + k8);
        float4 a = p[0], b = p[1];
        v[0]=a.x; v[1]=a.y; v[2]=a.z; v[3]=a.w; v[4]=b.x; v[5]=b.y; v[6]=b.z; v[7]=b.w;
    } else {
        const float4* p = reinterpret_cast<const float4*>(
            spline_w + (size_t)o * (I_FEAT * G_KNOT) + (k8 - I_FEAT));
        float4 a = p[0], b = p[1];
        v[0]=0.1f*a.x; v[1]=0.1f*a.y; v[2]=0.1f*a.z; v[3]=0.1f*a.w;
        v[4]=0.1f*b.x; v[5]=0.1f*b.y; v[6]=0.1f*b.z; v[7]=0.1f*b.w;
    }
    Pack8 h;
#pragma unroll
    for (int j = 0; j < 8; ++j) h.v[j] = __float2half(v[j]);
    *reinterpret_cast<Pack8*>(&g_B[(size_t)o * K_EXT + k8]) = h;
}

// grid (K_EXT/2048, B_ROWS), 256 thr
__global__ void prep_x_kernel(const float* __restrict__ x,
                              const float* __restrict__ knots) {
    const int b = blockIdx.y;
    const int k8 = (blockIdx.x * 256 + threadIdx.x) * 8;
    float v[8];
    if (blockIdx.x == 0) {
        const float4* p = reinterpret_cast<const float4*>(x + (size_t)b * I_FEAT + k8);
        float4 a = p[0], c = p[1];
        v[0]=a.x; v[1]=a.y; v[2]=a.z; v[3]=a.w; v[4]=c.x; v[5]=c.y; v[6]=c.z; v[7]=c.w;
    } else {
        const int i = (k8 - I_FEAT) >> 3;
        const float xv = __ldg(&x[(size_t)b * I_FEAT + i]);
        const float4 kn0 = *reinterpret_cast<const float4*>(knots);
        const float4 kn1 = *(reinterpret_cast<const float4*>(knots) + 1);
        v[0]=fmaxf(xv-kn0.x,0.f); v[1]=fmaxf(xv-kn0.y,0.f);
        v[2]=fmaxf(xv-kn0.z,0.f); v[3]=fmaxf(xv-kn0.w,0.f);
        v[4]=fmaxf(xv-kn1.x,0.f); v[5]=fmaxf(xv-kn1.y,0.f);
        v[6]=fmaxf(xv-kn1.z,0.f); v[7]=fmaxf(xv-kn1.w,0.f);
    }
    Pack8 h;
#pragma unroll
    for (int j = 0; j < 8; ++j) h.v[j] = __float2half(v[j]);
    *reinterpret_cast<Pack8*>(&g_A[(size_t)b * K_EXT + k8]) = h;
}

// ------------------------------ GEMM core -----------------------------------
// Raster over the 256-tile space (m_blk in 16 x n_blk in 16), m-groups of 4.
__device__ __forceinline__ void tile_coords(int p, int& mb, int& nb) {
    const int grp = p >> 6;          // 0..3
    const int inb = p & 63;
    mb = grp * 4 + (inb & 3);        // 0..15
    nb = inb >> 2;                   // 0..15
}

// Stage layout (k-halves of 64 cols = 128B rows, SW128 XOR swizzle):
//   A0 @0 (MT*128), A1 @MT*128, B0 @MT*256 (NT*128), B1 @MT*256+NT*128
// STAGE = MT*256 + NT*256.
template <int MT, int NT>
__device__ __forceinline__ void load_chunk(const __half* gA, const __half* gB,
                                           uint32_t st, int tid) {
#pragma unroll
    for (int h = 0; h < 2; ++h) {
#pragma unroll
        for (int i = 0; i < MT / 32; ++i) {
            const int idx = tid + i * 256;
            const int row = idx >> 3;
            const int sub = idx & 7;
            const uint32_t off = (uint32_t)(row * 128 + sub * 16);
            const uint32_t sw = off ^ ((off >> 3) & 0x70u);
            CP_ASYNC16(st + h * (MT * 128) + sw,
                       reinterpret_cast<const char*>(gA) +
                           (size_t)row * (K_EXT * 2) + h * 128 + sub * 16);
        }
#pragma unroll
        for (int i = 0; i < NT / 32; ++i) {
            const int idx = tid + i * 256;
            const int row = idx >> 3;
            const int sub = idx & 7;
            const uint32_t off = (uint32_t)(row * 128 + sub * 16);
            const uint32_t sw = off ^ ((off >> 3) & 0x70u);
            CP_ASYNC16(st + MT * 256 + h * (NT * 128) + sw,
                       reinterpret_cast<const char*>(gB) +
                           (size_t)row * (K_EXT * 2) + h * 128 + sub * 16);
        }
    }
}

template <int MT, int NT>
__device__ __forceinline__ void gemm_tile(float* __restrict__ out,
                                          size_t m0, size_t n0,
                                          uint32_t sm0, int tid) {
    constexpr int MF = MT / 64;          // A m16-frags per warp
    constexpr int NF = NT / 16;          // n8-frags per warp
    constexpr int BL = NT / 32;          // B LDSM.x4 per warp
    constexpr uint32_t STAGE = (uint32_t)(MT * 256 + NT * 256);

    const int lane = tid & 31;
    const int warp = tid >> 5;
    const int wm = warp & 3;             // 4 warps along M
    const int wn = warp >> 2;            // 2 warps along N

    const __half* pA = g_A + m0 * K_EXT;
    const __half* pB = g_B + n0 * K_EXT;

    float acc[MF][NF][4] = {};

    const int a_lr = (lane & 7) | (((lane >> 3) & 1) << 3);
    const int a_ko = (lane >> 4) << 4;
    const int b_lr = (lane & 7) | (((lane >> 4) & 1) << 3);
    const int b_ko = ((lane >> 3) & 1) << 4;
    const uint32_t xorl = (uint32_t)((lane & 7) << 4);

    uint32_t a_rowoff[MF], b_rowoff[BL];
#pragma unroll
    for (int mt = 0; mt < MF; ++mt)
        a_rowoff[mt] = (uint32_t)((wm * (MT / 4) + mt * 16 + a_lr) * 128);
#pragma unroll
    for (int nt2 = 0; nt2 < BL; ++nt2)
        b_rowoff[nt2] = (uint32_t)((wn * (NT / 2) + nt2 * 16 + b_lr) * 128);

    load_chunk<MT, NT>(pA, pB, sm0, tid);
    CP_COMMIT();

    for (int c = 0; c < N_CHUNKS; ++c) {
        if (c + 1 < N_CHUNKS) {
            const int k1 = (c + 1) * K_CHUNK;
            load_chunk<MT, NT>(pA + k1, pB + k1,
                               sm0 + (uint32_t)(((c + 1) & 1)) * STAGE, tid);
        }
        CP_COMMIT();
        CP_WAIT1();
        __syncthreads();

        const uint32_t sb = sm0 + (uint32_t)((c & 1)) * STAGE;

        uint32_t ah[2][MF][4], bh[2][BL][4];

#define LOAD_FRAGS(ks, buf)                                                    \
        do {                                                                   \
            const uint32_t _ha = (uint32_t)(((ks) >> 2) * (MT * 128));         \
            const uint32_t _hb = (uint32_t)(((ks) >> 2) * (NT * 128));         \
            const uint32_t _kb = (uint32_t)(((ks) & 3) * 32);                  \
            const uint32_t _kA = (_kb + a_ko) ^ xorl;                          \
            const uint32_t _kB = (_kb + b_ko) ^ xorl;                          \
            _Pragma("unroll")                                                  \
            for (int _mt = 0; _mt < MF; ++_mt)                                 \
                LDSM4(ah[buf][_mt], sb + _ha + a_rowoff[_mt] + _kA);           \
            _Pragma("unroll")                                                  \
            for (int _nt = 0; _nt < BL; ++_nt)                                 \
                LDSM4(bh[buf][_nt],                                           \
                      sb + (uint32_t)(MT * 256) + _hb + b_rowoff[_nt] + _kB);  \
        } while (0)

        LOAD_FRAGS(0, 0);
#pragma unroll
        for (int ks = 0; ks < 8; ++ks) {
            if (ks < 7) LOAD_FRAGS(ks + 1, (ks + 1) & 1);
            const int cur = ks & 1;
#pragma unroll
            for (int mt = 0; mt < MF; ++mt)
#pragma unroll
                for (int nt = 0; nt < NF; ++nt)
                    MMA_F16(acc[mt][nt], ah[cur][mt],
                            &bh[cur][nt >> 1][(nt & 1) * 2]);
        }
#undef LOAD_FRAGS
        __syncthreads();
    }

    const int r = lane >> 2;
    const int cp2 = (lane & 3) * 2;
#pragma unroll
    for (int mt = 0; mt < MF; ++mt) {
        const size_t row = m0 + wm * (MT / 4) + mt * 16 + r;
#pragma unroll
        for (int nt = 0; nt < NF; ++nt) {
            const size_t col = n0 + wn * (NT / 2) + nt * 8 + cp2;
            *reinterpret_cast<float2*>(&out[row * O_COLS + col]) =
                make_float2(acc[mt][nt][0], acc[mt][nt][1]);
            *reinterpret_cast<float2*>(&out[(row + 8) * O_COLS + col]) =
                make_float2(acc[mt][nt][2], acc[mt][nt][3]);
        }
    }
}

// Full tiles: raster positions [0, N_FULL), 256x128, 192KB smem, 1 CTA/SM.
__global__ void __launch_bounds__(256, 1) kan_gemm_full(float* __restrict__ out) {
    extern __shared__ char smem[];
    int mb, nb;
    tile_coords(blockIdx.x, mb, nb);
    gemm_tile<256, 128>(out, (size_t)mb * 256, (size_t)nb * 128,
                        smem_to_u32(smem), threadIdx.x);
}

// Quarter tiles: raster positions [N_FULL, 256) split 2x2 -> 128x64 quarters.
// 96KB smem -> 2 CTAs/SM.
__global__ void __launch_bounds__(256, 2) kan_gemm_quarter(float* __restrict__ out) {
    extern __shared__ char smem[];
    const int q = blockIdx.x;              // 0..431
    int mb, nb;
    tile_coords(N_FULL + (q >> 2), mb, nb);
    const int sub = q & 3;
    const size_t m0 = (size_t)mb * 256 + (size_t)(sub >> 1) * 128;
    const size_t n0 = (size_t)nb * 128 + (size_t)(sub & 1) * 64;
    gemm_tile<128, 64>(out, m0, n0, smem_to_u32(smem), threadIdx.x);
}

// ------------------------------- launch -------------------------------------

extern "C" void kernel_launch(void* const* d_in, const int* in_sizes, int n_in,
                              void* d_out, int out_size) {
    const float* x        = (const float*)d_in[0];
    const float* base_w   = (const float*)d_in[1];
    const float* spline_w = (const float*)d_in[2];
    const float* knots    = (const float*)d_in[3];
    float* out = (float*)d_out;

    prep_w_kernel<<<dim3(K_EXT / 2048, O_COLS), 256>>>(base_w, spline_w);
    prep_x_kernel<<<dim3(K_EXT / 2048, B_ROWS), 256>>>(x, knots);

    const int smem_full = 256 * 256 + 128 * 256;   // 98304... x2 stages below
    const int full_bytes = 2 * (256 * 256 + 128 * 256);     // 196608
    const int quarter_bytes = 2 * (128 * 256 + 64 * 256);   // 98304
    cudaFuncSetAttribute(kan_gemm_full,
                         cudaFuncAttributeMaxDynamicSharedMemorySize, full_bytes);
    cudaFuncSetAttribute(kan_gemm_quarter,
                         cudaFuncAttributeMaxDynamicSharedMemorySize, quarter_bytes);
    (void)smem_full;

    kan_gemm_full<<<N_FULL, 256, full_bytes>>>(out);
    kan_gemm_quarter<<<(256 - N_FULL) * 4, 256, quarter_bytes>>>(out);
}

// round 8
// speedup vs baseline: 3.2811x; 1.0391x over previous
#include <cuda_runtime.h>
#include <cuda_fp16.h>
#include <cstdint>
#include <cstddef>

// ---------------------------------------------------------------------------
// KANLayer as one big GEMM (mma.sync fp16, single product):
//   out[4096,2048] = X_ext[4096,18432] @ W_ext[2048,18432]^T
// Round 8: persistent balanced schedule. 148 CTAs (1/SM). Each CTA:
//   (a) one full 256x128 tile (tiles 0..147)
//   (b) a contiguous ~105-chunk slice of the 108 tail tiles' K-chunk space,
//       written as fp32 partials -> tiny deterministic combine kernel.
// Removes wave quantization (1.73 -> 2.0 slots) AND the inter-phase barrier.
// ---------------------------------------------------------------------------

#define B_ROWS 4096
#define O_COLS 2048
#define I_FEAT 2048
#define G_KNOT 8
#define K_EXT  (I_FEAT + I_FEAT * G_KNOT)   // 18432
#define K_CHUNK 128
#define N_CHUNKS (K_EXT / K_CHUNK)           // 144 per tile

#define N_SM 148
#define N_TAIL_TILES 108                     // tiles 148..255
#define TAIL_UNITS (N_TAIL_TILES * N_CHUNKS) // 15552

#define M_TILE 256
#define N_TILE 128
// stage: [A0 32K][A1 32K][B0 16K][B1 16K] = 96KB
#define STAGE_BYTES 98304
#define SMEM_BYTES (2 * STAGE_BYTES)         // 196608

__device__ __half g_A[(size_t)B_ROWS * K_EXT];
__device__ __half g_B[(size_t)O_COLS * K_EXT];
// per-CTA partial tiles: 148 CTAs x 2 slots x (256x128) fp32
__device__ float g_part[(size_t)N_SM * 2 * M_TILE * N_TILE];

// ------------------------------ PTX helpers --------------------------------
__device__ __forceinline__ uint32_t smem_to_u32(const void* p) {
    uint32_t a;
    asm("{ .reg .u64 t; cvta.to.shared.u64 t, %1; cvt.u32.u64 %0, t; }"
        : "=r"(a) : "l"(p));
    return a;
}

#define CP_ASYNC16(dst, src) \
    asm volatile("cp.async.cg.shared.global [%0], [%1], 16;" \
                 :: "r"(dst), "l"(src))
#define CP_COMMIT() asm volatile("cp.async.commit_group;" ::: "memory")
#define CP_WAIT1()  asm volatile("cp.async.wait_group 1;" ::: "memory")

#define LDSM4(r, addr) \
    asm volatile("ldmatrix.sync.aligned.m8n8.x4.shared.b16 {%0,%1,%2,%3}, [%4];" \
        : "=r"((r)[0]), "=r"((r)[1]), "=r"((r)[2]), "=r"((r)[3]) : "r"(addr))

#define MMA_F16(d, a, b) \
    asm volatile("mma.sync.aligned.m16n8k16.row.col.f32.f16.f16.f32 " \
        "{%0,%1,%2,%3}, {%4,%5,%6,%7}, {%8,%9}, {%0,%1,%2,%3};" \
        : "+f"((d)[0]), "+f"((d)[1]), "+f"((d)[2]), "+f"((d)[3]) \
        : "r"((a)[0]), "r"((a)[1]), "r"((a)[2]), "r"((a)[3]), \
          "r"((b)[0]), "r"((b)[1]))

// --------------------------- preprocessing (merged) -------------------------

struct alignas(16) Pack8 { __half v[8]; };

// grid (K_EXT/2048, O_COLS + B_ROWS), 256 thr; thread -> 8 consecutive k
__global__ void prep_kernel(const float* __restrict__ x,
                            const float* __restrict__ base_w,
                            const float* __restrict__ spline_w,
                            const float* __restrict__ knots) {
    const int row = blockIdx.y;
    const int k8 = (blockIdx.x * 256 + threadIdx.x) * 8;
    float v[8];
    if (row < O_COLS) {                      // ---- W_ext row ----
        const int o = row;
        if (blockIdx.x == 0) {
            const float4* p = reinterpret_cast<const float4*>(base_w + (size_t)o * I_FEAT + k8);
            float4 a = p[0], b = p[1];
            v[0]=a.x; v[1]=a.y; v[2]=a.z; v[3]=a.w; v[4]=b.x; v[5]=b.y; v[6]=b.z; v[7]=b.w;
        } else {
            const float4* p = reinterpret_cast<const float4*>(
                spline_w + (size_t)o * (I_FEAT * G_KNOT) + (k8 - I_FEAT));
            float4 a = p[0], b = p[1];
            v[0]=0.1f*a.x; v[1]=0.1f*a.y; v[2]=0.1f*a.z; v[3]=0.1f*a.w;
            v[4]=0.1f*b.x; v[5]=0.1f*b.y; v[6]=0.1f*b.z; v[7]=0.1f*b.w;
        }
        Pack8 h;
#pragma unroll
        for (int jj = 0; jj < 8; ++jj) h.v[jj] = __float2half(v[jj]);
        *reinterpret_cast<Pack8*>(&g_B[(size_t)o * K_EXT + k8]) = h;
    } else {                                 // ---- X_ext row ----
        const int b = row - O_COLS;
        if (blockIdx.x == 0) {
            const float4* p = reinterpret_cast<const float4*>(x + (size_t)b * I_FEAT + k8);
            float4 a = p[0], c = p[1];
            v[0]=a.x; v[1]=a.y; v[2]=a.z; v[3]=a.w; v[4]=c.x; v[5]=c.y; v[6]=c.z; v[7]=c.w;
        } else {
            const int i = (k8 - I_FEAT) >> 3;
            const float xv = __ldg(&x[(size_t)b * I_FEAT + i]);
            const float4 kn0 = *reinterpret_cast<const float4*>(knots);
            const float4 kn1 = *(reinterpret_cast<const float4*>(knots) + 1);
            v[0]=fmaxf(xv-kn0.x,0.f); v[1]=fmaxf(xv-kn0.y,0.f);
            v[2]=fmaxf(xv-kn0.z,0.f); v[3]=fmaxf(xv-kn0.w,0.f);
            v[4]=fmaxf(xv-kn1.x,0.f); v[5]=fmaxf(xv-kn1.y,0.f);
            v[6]=fmaxf(xv-kn1.z,0.f); v[7]=fmaxf(xv-kn1.w,0.f);
        }
        Pack8 h;
#pragma unroll
        for (int jj = 0; jj < 8; ++jj) h.v[jj] = __float2half(v[jj]);
        *reinterpret_cast<Pack8*>(&g_A[(size_t)b * K_EXT + k8]) = h;
    }
}

// ------------------------------ GEMM core -----------------------------------
// Raster over 256 tiles (m_blk 0..15, n_blk 0..15), m-groups of 4.
__device__ __forceinline__ void tile_coords(int p, int& mb, int& nb) {
    const int grp = p >> 6;
    const int inb = p & 63;
    mb = grp * 4 + (inb & 3);
    nb = inb >> 2;
}

// Load one 128-col K-chunk of A(256 rows) + B(128 rows) into a stage.
__device__ __forceinline__ void load_chunk(const __half* gA, const __half* gB,
                                           uint32_t st, int tid) {
#pragma unroll
    for (int h = 0; h < 2; ++h) {
#pragma unroll
        for (int i = 0; i < 8; ++i) {
            const int idx = tid + i * 256;
            const int row = idx >> 3;
            const int sub = idx & 7;
            const uint32_t off = (uint32_t)(row * 128 + sub * 16);
            const uint32_t sw = off ^ ((off >> 3) & 0x70u);
            CP_ASYNC16(st + h * 32768 + sw,
                       reinterpret_cast<const char*>(gA) +
                           (size_t)row * (K_EXT * 2) + h * 128 + sub * 16);
        }
#pragma unroll
        for (int i = 0; i < 4; ++i) {
            const int idx = tid + i * 256;
            const int row = idx >> 3;
            const int sub = idx & 7;
            const uint32_t off = (uint32_t)(row * 128 + sub * 16);
            const uint32_t sw = off ^ ((off >> 3) & 0x70u);
            CP_ASYNC16(st + 65536 + h * 16384 + sw,
                       reinterpret_cast<const char*>(gB) +
                           (size_t)row * (K_EXT * 2) + h * 128 + sub * 16);
        }
    }
}

// Compute chunks [c0, c1) of tile (m0, n0); add into dst (stride dstride).
__device__ __forceinline__ void gemm_range(size_t m0, size_t n0, int c0, int c1,
                                           float* __restrict__ dst, int dstride,
                                           uint32_t sm0, int tid) {
    const int lane = tid & 31;
    const int warp = tid >> 5;
    const int wm = warp & 3;             // 4 warps along M (64 rows)
    const int wn = warp >> 2;            // 2 warps along N (64 cols)

    const __half* pA = g_A + m0 * K_EXT;
    const __half* pB = g_B + n0 * K_EXT;

    float acc[4][8][4] = {};

    const int a_lr = (lane & 7) | (((lane >> 3) & 1) << 3);
    const int a_ko = (lane >> 4) << 4;
    const int b_lr = (lane & 7) | (((lane >> 4) & 1) << 3);
    const int b_ko = ((lane >> 3) & 1) << 4;
    const uint32_t xorl = (uint32_t)((lane & 7) << 4);

    uint32_t a_rowoff[4], b_rowoff[4];
#pragma unroll
    for (int mt = 0; mt < 4; ++mt)
        a_rowoff[mt] = (uint32_t)((wm * 64 + mt * 16 + a_lr) * 128);
#pragma unroll
    for (int nt2 = 0; nt2 < 4; ++nt2)
        b_rowoff[nt2] = (uint32_t)((wn * 64 + nt2 * 16 + b_lr) * 128);

    load_chunk(pA + (size_t)c0 * K_CHUNK, pB + (size_t)c0 * K_CHUNK,
               sm0 + (uint32_t)((c0 & 1)) * STAGE_BYTES, tid);
    CP_COMMIT();

    for (int c = c0; c < c1; ++c) {
        if (c + 1 < c1) {
            const size_t k1 = (size_t)(c + 1) * K_CHUNK;
            load_chunk(pA + k1, pB + k1,
                       sm0 + (uint32_t)(((c + 1) & 1)) * STAGE_BYTES, tid);
        }
        CP_COMMIT();
        CP_WAIT1();
        __syncthreads();

        const uint32_t sb = sm0 + (uint32_t)((c & 1)) * STAGE_BYTES;

        uint32_t ah[2][4][4], bh[2][4][4];

#define LOAD_FRAGS(ks, buf)                                                    \
        do {                                                                   \
            const uint32_t _ha = (uint32_t)(((ks) >> 2) * 32768);              \
            const uint32_t _hb = (uint32_t)(((ks) >> 2) * 16384);              \
            const uint32_t _kb = (uint32_t)(((ks) & 3) * 32);                  \
            const uint32_t _kA = (_kb + a_ko) ^ xorl;                          \
            const uint32_t _kB = (_kb + b_ko) ^ xorl;                          \
            _Pragma("unroll")                                                  \
            for (int _mt = 0; _mt < 4; ++_mt)                                  \
                LDSM4(ah[buf][_mt], sb + _ha + a_rowoff[_mt] + _kA);           \
            _Pragma("unroll")                                                  \
            for (int _nt = 0; _nt < 4; ++_nt)                                  \
                LDSM4(bh[buf][_nt], sb + 65536 + _hb + b_rowoff[_nt] + _kB);   \
        } while (0)

        LOAD_FRAGS(0, 0);
#pragma unroll
        for (int ks = 0; ks < 8; ++ks) {
            if (ks < 7) LOAD_FRAGS(ks + 1, (ks + 1) & 1);
            const int cur = ks & 1;
#pragma unroll
            for (int mt = 0; mt < 4; ++mt)
#pragma unroll
                for (int nt = 0; nt < 8; ++nt)
                    MMA_F16(acc[mt][nt], ah[cur][mt],
                            &bh[cur][nt >> 1][(nt & 1) * 2]);
        }
#undef LOAD_FRAGS
        __syncthreads();
    }

    // Epilogue: direct stores (dst pre-offset to tile origin)
    const int r = lane >> 2;
    const int cp2 = (lane & 3) * 2;
#pragma unroll
    for (int mt = 0; mt < 4; ++mt) {
        const int row = wm * 64 + mt * 16 + r;
#pragma unroll
        for (int nt = 0; nt < 8; ++nt) {
            const int col = wn * 64 + nt * 8 + cp2;
            *reinterpret_cast<float2*>(&dst[(size_t)row * dstride + col]) =
                make_float2(acc[mt][nt][0], acc[mt][nt][1]);
            *reinterpret_cast<float2*>(&dst[(size_t)(row + 8) * dstride + col]) =
                make_float2(acc[mt][nt][2], acc[mt][nt][3]);
        }
    }
}

// Persistent kernel: CTA j = full tile j, then tail slice j.
__global__ void __launch_bounds__(256, 1) kan_gemm_persist(float* __restrict__ out) {
    extern __shared__ char smem[];
    const uint32_t sm0 = smem_to_u32(smem);
    const int tid = threadIdx.x;
    const int j = blockIdx.x;                 // 0..147

    int mb, nb;
    tile_coords(j, mb, nb);
    gemm_range((size_t)mb * M_TILE, (size_t)nb * N_TILE, 0, N_CHUNKS,
               out + (size_t)mb * M_TILE * O_COLS + (size_t)nb * N_TILE,
               O_COLS, sm0, tid);

    // tail slice: chunk-units [j*15552/148, (j+1)*15552/148)
    int s = (j * TAIL_UNITS) / N_SM;
    const int e = ((j + 1) * TAIL_UNITS) / N_SM;
    int sl = 0;
    while (s < e) {
        const int t = s / N_CHUNKS;                       // tail tile index
        const int seg_end = min(e, (t + 1) * N_CHUNKS);
        tile_coords(N_SM + t, mb, nb);
        gemm_range((size_t)mb * M_TILE, (size_t)nb * N_TILE,
                   s - t * N_CHUNKS, seg_end - t * N_CHUNKS,
                   g_part + ((size_t)j * 2 + sl) * (M_TILE * N_TILE),
                   N_TILE, sm0, tid);
        s = seg_end;
        ++sl;
    }
}

// Combine: tail tile t = sum of its 1..3 partial segments (ascending j).
// grid = N_TAIL_TILES * 128 blocks, 256 thr; 1 element/thread.
__global__ void __launch_bounds__(256) kan_combine(float* __restrict__ out) {
    const int b = blockIdx.x;
    const int t = b >> 7;
    const int local = ((b & 127) << 8) | threadIdx.x;     // 0..32767
    const int unit0 = t * N_CHUNKS;
    const int unit1 = unit0 + N_CHUNKS;

    int j = (unit0 * N_SM) / TAIL_UNITS;
    while (((j + 1) * TAIL_UNITS) / N_SM <= unit0) ++j;

    float s = 0.0f;
    while (j < N_SM) {
        const int sj = (j * TAIL_UNITS) / N_SM;
        if (sj >= unit1) break;
        const int sl = (sj / N_CHUNKS == t) ? 0 : 1;
        s += g_part[((size_t)j * 2 + sl) * (M_TILE * N_TILE) + local];
        ++j;
    }

    int mb, nb;
    tile_coords(N_SM + t, mb, nb);
    const int r = local >> 7;
    const int c = local & 127;
    out[(size_t)(mb * M_TILE + r) * O_COLS + nb * N_TILE + c] = s;
}

// ------------------------------- launch -------------------------------------

extern "C" void kernel_launch(void* const* d_in, const int* in_sizes, int n_in,
                              void* d_out, int out_size) {
    const float* x        = (const float*)d_in[0];
    const float* base_w   = (const float*)d_in[1];
    const float* spline_w = (const float*)d_in[2];
    const float* knots    = (const float*)d_in[3];
    float* out = (float*)d_out;

    prep_kernel<<<dim3(K_EXT / 2048, O_COLS + B_ROWS), 256>>>(x, base_w, spline_w, knots);

    cudaFuncSetAttribute(kan_gemm_persist,
                         cudaFuncAttributeMaxDynamicSharedMemorySize, SMEM_BYTES);
    kan_gemm_persist<<<N_SM, 256, SMEM_BYTES>>>(out);
    kan_combine<<<N_TAIL_TILES * 128, 256>>>(out);
}

// round 9
// speedup vs baseline: 3.3262x; 1.0138x over previous
#include <cuda_runtime.h>
#include <cuda_fp16.h>
#include <cstdint>
#include <cstddef>

// ---------------------------------------------------------------------------
// KANLayer as one big GEMM (mma.sync fp16, single product):
//   out[4096,2048] = X_ext[4096,18432] @ W_ext[2048,18432]^T
// Round 9: 512 threads/CTA (4 warps per SMSP) to raise tensor-issue
// utilization; warp tile 64x32, single-buffered fragments (reg budget 128).
// Persistent balanced schedule (148 CTAs: full tile + tail K-slice) + combine.
// ---------------------------------------------------------------------------

#define B_ROWS 4096
#define O_COLS 2048
#define I_FEAT 2048
#define G_KNOT 8
#define K_EXT  (I_FEAT + I_FEAT * G_KNOT)   // 18432
#define K_CHUNK 128
#define N_CHUNKS (K_EXT / K_CHUNK)           // 144 per tile

#define N_SM 148
#define N_TAIL_TILES 108                     // tiles 148..255
#define TAIL_UNITS (N_TAIL_TILES * N_CHUNKS) // 15552

#define M_TILE 256
#define N_TILE 128
#define THREADS 512
// stage: [A0 32K][A1 32K][B0 16K][B1 16K] = 96KB
#define STAGE_BYTES 98304
#define SMEM_BYTES (2 * STAGE_BYTES)         // 196608

__device__ __half g_A[(size_t)B_ROWS * K_EXT];
__device__ __half g_B[(size_t)O_COLS * K_EXT];
// per-CTA partial tiles: 148 CTAs x 2 slots x (256x128) fp32
__device__ float g_part[(size_t)N_SM * 2 * M_TILE * N_TILE];

// ------------------------------ PTX helpers --------------------------------
__device__ __forceinline__ uint32_t smem_to_u32(const void* p) {
    uint32_t a;
    asm("{ .reg .u64 t; cvta.to.shared.u64 t, %1; cvt.u32.u64 %0, t; }"
        : "=r"(a) : "l"(p));
    return a;
}

#define CP_ASYNC16(dst, src) \
    asm volatile("cp.async.cg.shared.global [%0], [%1], 16;" \
                 :: "r"(dst), "l"(src))
#define CP_COMMIT() asm volatile("cp.async.commit_group;" ::: "memory")
#define CP_WAIT1()  asm volatile("cp.async.wait_group 1;" ::: "memory")

#define LDSM4(r, addr) \
    asm volatile("ldmatrix.sync.aligned.m8n8.x4.shared.b16 {%0,%1,%2,%3}, [%4];" \
        : "=r"((r)[0]), "=r"((r)[1]), "=r"((r)[2]), "=r"((r)[3]) : "r"(addr))

#define MMA_F16(d, a, b) \
    asm volatile("mma.sync.aligned.m16n8k16.row.col.f32.f16.f16.f32 " \
        "{%0,%1,%2,%3}, {%4,%5,%6,%7}, {%8,%9}, {%0,%1,%2,%3};" \
        : "+f"((d)[0]), "+f"((d)[1]), "+f"((d)[2]), "+f"((d)[3]) \
        : "r"((a)[0]), "r"((a)[1]), "r"((a)[2]), "r"((a)[3]), \
          "r"((b)[0]), "r"((b)[1]))

// --------------------------- preprocessing (merged) -------------------------

struct alignas(16) Pack8 { __half v[8]; };

// grid (K_EXT/2048, O_COLS + B_ROWS), 256 thr; thread -> 8 consecutive k
__global__ void prep_kernel(const float* __restrict__ x,
                            const float* __restrict__ base_w,
                            const float* __restrict__ spline_w,
                            const float* __restrict__ knots) {
    const int row = blockIdx.y;
    const int k8 = (blockIdx.x * 256 + threadIdx.x) * 8;
    float v[8];
    if (row < O_COLS) {                      // ---- W_ext row ----
        const int o = row;
        if (blockIdx.x == 0) {
            const float4* p = reinterpret_cast<const float4*>(base_w + (size_t)o * I_FEAT + k8);
            float4 a = p[0], b = p[1];
            v[0]=a.x; v[1]=a.y; v[2]=a.z; v[3]=a.w; v[4]=b.x; v[5]=b.y; v[6]=b.z; v[7]=b.w;
        } else {
            const float4* p = reinterpret_cast<const float4*>(
                spline_w + (size_t)o * (I_FEAT * G_KNOT) + (k8 - I_FEAT));
            float4 a = p[0], b = p[1];
            v[0]=0.1f*a.x; v[1]=0.1f*a.y; v[2]=0.1f*a.z; v[3]=0.1f*a.w;
            v[4]=0.1f*b.x; v[5]=0.1f*b.y; v[6]=0.1f*b.z; v[7]=0.1f*b.w;
        }
        Pack8 h;
#pragma unroll
        for (int jj = 0; jj < 8; ++jj) h.v[jj] = __float2half(v[jj]);
        *reinterpret_cast<Pack8*>(&g_B[(size_t)o * K_EXT + k8]) = h;
    } else {                                 // ---- X_ext row ----
        const int b = row - O_COLS;
        if (blockIdx.x == 0) {
            const float4* p = reinterpret_cast<const float4*>(x + (size_t)b * I_FEAT + k8);
            float4 a = p[0], c = p[1];
            v[0]=a.x; v[1]=a.y; v[2]=a.z; v[3]=a.w; v[4]=c.x; v[5]=c.y; v[6]=c.z; v[7]=c.w;
        } else {
            const int i = (k8 - I_FEAT) >> 3;
            const float xv = __ldg(&x[(size_t)b * I_FEAT + i]);
            const float4 kn0 = *reinterpret_cast<const float4*>(knots);
            const float4 kn1 = *(reinterpret_cast<const float4*>(knots) + 1);
            v[0]=fmaxf(xv-kn0.x,0.f); v[1]=fmaxf(xv-kn0.y,0.f);
            v[2]=fmaxf(xv-kn0.z,0.f); v[3]=fmaxf(xv-kn0.w,0.f);
            v[4]=fmaxf(xv-kn1.x,0.f); v[5]=fmaxf(xv-kn1.y,0.f);
            v[6]=fmaxf(xv-kn1.z,0.f); v[7]=fmaxf(xv-kn1.w,0.f);
        }
        Pack8 h;
#pragma unroll
        for (int jj = 0; jj < 8; ++jj) h.v[jj] = __float2half(v[jj]);
        *reinterpret_cast<Pack8*>(&g_A[(size_t)b * K_EXT + k8]) = h;
    }
}

// ------------------------------ GEMM core -----------------------------------
__device__ __forceinline__ void tile_coords(int p, int& mb, int& nb) {
    const int grp = p >> 6;
    const int inb = p & 63;
    mb = grp * 4 + (inb & 3);
    nb = inb >> 2;
}

// Load one 128-col K-chunk of A(256 rows) + B(128 rows) into a stage. 512 thr.
__device__ __forceinline__ void load_chunk(const __half* gA, const __half* gB,
                                           uint32_t st, int tid) {
#pragma unroll
    for (int h = 0; h < 2; ++h) {
#pragma unroll
        for (int i = 0; i < 4; ++i) {        // A: 2048 16B pieces per half
            const int idx = tid + i * THREADS;
            const int row = idx >> 3;
            const int sub = idx & 7;
            const uint32_t off = (uint32_t)(row * 128 + sub * 16);
            const uint32_t sw = off ^ ((off >> 3) & 0x70u);
            CP_ASYNC16(st + h * 32768 + sw,
                       reinterpret_cast<const char*>(gA) +
                           (size_t)row * (K_EXT * 2) + h * 128 + sub * 16);
        }
#pragma unroll
        for (int i = 0; i < 2; ++i) {        // B: 1024 pieces per half
            const int idx = tid + i * THREADS;
            const int row = idx >> 3;
            const int sub = idx & 7;
            const uint32_t off = (uint32_t)(row * 128 + sub * 16);
            const uint32_t sw = off ^ ((off >> 3) & 0x70u);
            CP_ASYNC16(st + 65536 + h * 16384 + sw,
                       reinterpret_cast<const char*>(gB) +
                           (size_t)row * (K_EXT * 2) + h * 128 + sub * 16);
        }
    }
}

// Compute chunks [c0, c1) of tile (m0, n0); write into dst (stride dstride).
// 16 warps: wm = warp&3 (64 M-rows each), wn = warp>>2 (32 N-cols each).
__device__ __forceinline__ void gemm_range(size_t m0, size_t n0, int c0, int c1,
                                           float* __restrict__ dst, int dstride,
                                           uint32_t sm0, int tid) {
    const int lane = tid & 31;
    const int warp = tid >> 5;
    const int wm = warp & 3;
    const int wn = warp >> 2;

    const __half* pA = g_A + m0 * K_EXT;
    const __half* pB = g_B + n0 * K_EXT;

    float acc[4][4][4] = {};

    const int a_lr = (lane & 7) | (((lane >> 3) & 1) << 3);
    const int a_ko = (lane >> 4) << 4;
    const int b_lr = (lane & 7) | (((lane >> 4) & 1) << 3);
    const int b_ko = ((lane >> 3) & 1) << 4;
    const uint32_t xorl = (uint32_t)((lane & 7) << 4);

    uint32_t a_rowoff[4], b_rowoff[2];
#pragma unroll
    for (int mt = 0; mt < 4; ++mt)
        a_rowoff[mt] = (uint32_t)((wm * 64 + mt * 16 + a_lr) * 128);
#pragma unroll
    for (int nt2 = 0; nt2 < 2; ++nt2)
        b_rowoff[nt2] = (uint32_t)((wn * 32 + nt2 * 16 + b_lr) * 128);

    load_chunk(pA + (size_t)c0 * K_CHUNK, pB + (size_t)c0 * K_CHUNK,
               sm0 + (uint32_t)((c0 & 1)) * STAGE_BYTES, tid);
    CP_COMMIT();

    for (int c = c0; c < c1; ++c) {
        if (c + 1 < c1) {
            const size_t k1 = (size_t)(c + 1) * K_CHUNK;
            load_chunk(pA + k1, pB + k1,
                       sm0 + (uint32_t)(((c + 1) & 1)) * STAGE_BYTES, tid);
        }
        CP_COMMIT();
        CP_WAIT1();
        __syncthreads();

        const uint32_t sb = sm0 + (uint32_t)((c & 1)) * STAGE_BYTES;

#pragma unroll
        for (int ks = 0; ks < 8; ++ks) {
            const uint32_t ha = (uint32_t)((ks >> 2) * 32768);
            const uint32_t hb = (uint32_t)((ks >> 2) * 16384);
            const uint32_t kb = (uint32_t)((ks & 3) * 32);
            const uint32_t kA = (kb + a_ko) ^ xorl;
            const uint32_t kB = (kb + b_ko) ^ xorl;

            uint32_t ah[4][4], bh[2][4];
#pragma unroll
            for (int mt = 0; mt < 4; ++mt)
                LDSM4(ah[mt], sb + ha + a_rowoff[mt] + kA);
#pragma unroll
            for (int nt2 = 0; nt2 < 2; ++nt2)
                LDSM4(bh[nt2], sb + 65536 + hb + b_rowoff[nt2] + kB);

#pragma unroll
            for (int mt = 0; mt < 4; ++mt)
#pragma unroll
                for (int nt = 0; nt < 4; ++nt)
                    MMA_F16(acc[mt][nt], ah[mt],
                            &bh[nt >> 1][(nt & 1) * 2]);
        }
        __syncthreads();
    }

    // Epilogue: direct stores (dst pre-offset to tile origin)
    const int r = lane >> 2;
    const int cp2 = (lane & 3) * 2;
#pragma unroll
    for (int mt = 0; mt < 4; ++mt) {
        const int row = wm * 64 + mt * 16 + r;
#pragma unroll
        for (int nt = 0; nt < 4; ++nt) {
            const int col = wn * 32 + nt * 8 + cp2;
            *reinterpret_cast<float2*>(&dst[(size_t)row * dstride + col]) =
                make_float2(acc[mt][nt][0], acc[mt][nt][1]);
            *reinterpret_cast<float2*>(&dst[(size_t)(row + 8) * dstride + col]) =
                make_float2(acc[mt][nt][2], acc[mt][nt][3]);
        }
    }
}

// Persistent kernel: CTA j = full tile j, then tail slice j.
__global__ void __launch_bounds__(THREADS, 1) kan_gemm_persist(float* __restrict__ out) {
    extern __shared__ char smem[];
    const uint32_t sm0 = smem_to_u32(smem);
    const int tid = threadIdx.x;
    const int j = blockIdx.x;                 // 0..147

    int mb, nb;
    tile_coords(j, mb, nb);
    gemm_range((size_t)mb * M_TILE, (size_t)nb * N_TILE, 0, N_CHUNKS,
               out + (size_t)mb * M_TILE * O_COLS + (size_t)nb * N_TILE,
               O_COLS, sm0, tid);

    // tail slice: chunk-units [j*15552/148, (j+1)*15552/148)
    int s = (j * TAIL_UNITS) / N_SM;
    const int e = ((j + 1) * TAIL_UNITS) / N_SM;
    int sl = 0;
    while (s < e) {
        const int t = s / N_CHUNKS;                       // tail tile index
        const int seg_end = min(e, (t + 1) * N_CHUNKS);
        tile_coords(N_SM + t, mb, nb);
        gemm_range((size_t)mb * M_TILE, (size_t)nb * N_TILE,
                   s - t * N_CHUNKS, seg_end - t * N_CHUNKS,
                   g_part + ((size_t)j * 2 + sl) * (M_TILE * N_TILE),
                   N_TILE, sm0, tid);
        s = seg_end;
        ++sl;
    }
}

// Combine: tail tile t = sum of its 1..3 partial segments (ascending j).
// grid = N_TAIL_TILES * 128 blocks, 256 thr; 1 element/thread.
__global__ void __launch_bounds__(256) kan_combine(float* __restrict__ out) {
    const int b = blockIdx.x;
    const int t = b >> 7;
    const int local = ((b & 127) << 8) | threadIdx.x;     // 0..32767
    const int unit0 = t * N_CHUNKS;
    const int unit1 = unit0 + N_CHUNKS;

    int j = (unit0 * N_SM) / TAIL_UNITS;
    while (((j + 1) * TAIL_UNITS) / N_SM <= unit0) ++j;

    float s = 0.0f;
    while (j < N_SM) {
        const int sj = (j * TAIL_UNITS) / N_SM;
        if (sj >= unit1) break;
        const int sl = (sj / N_CHUNKS == t) ? 0 : 1;
        s += g_part[((size_t)j * 2 + sl) * (M_TILE * N_TILE) + local];
        ++j;
    }

    int mb, nb;
    tile_coords(N_SM + t, mb, nb);
    const int r = local >> 7;
    const int c = local & 127;
    out[(size_t)(mb * M_TILE + r) * O_COLS + nb * N_TILE + c] = s;
}

// ------------------------------- launch -------------------------------------

extern "C" void kernel_launch(void* const* d_in, const int* in_sizes, int n_in,
                              void* d_out, int out_size) {
    const float* x        = (const float*)d_in[0];
    const float* base_w   = (const float*)d_in[1];
    const float* spline_w = (const float*)d_in[2];
    const float* knots    = (const float*)d_in[3];
    float* out = (float*)d_out;

    prep_kernel<<<dim3(K_EXT / 2048, O_COLS + B_ROWS), 256>>>(x, base_w, spline_w, knots);

    cudaFuncSetAttribute(kan_gemm_persist,
                         cudaFuncAttributeMaxDynamicSharedMemorySize, SMEM_BYTES);
    kan_gemm_persist<<<N_SM, THREADS, SMEM_BYTES>>>(out);
    kan_combine<<<N_TAIL_TILES * 128, 256>>>(out);
}